// round 3
// baseline (speedup 1.0000x reference)
#include <cuda_runtime.h>
#include <math.h>

// Problem constants
constexpr int BATCH = 8;
constexpr int SEQ   = 2048;
constexpr int DIM   = 128;
constexpr int BR    = 128;   // query rows per CTA
constexpr int BC    = 64;    // keys per chunk
constexpr float NEG_BIG = -10000.0f;
constexpr float SCALE   = 0.0883883476483184405f; // 1/sqrt(128)

// Scratch for Q,K,V projections (8 MB each; device globals = allowed scratch)
__device__ float g_q[BATCH * SEQ * DIM];
__device__ float g_k[BATCH * SEQ * DIM];
__device__ float g_v[BATCH * SEQ * DIM];

// ---------------------------------------------------------------------------
// Kernel 1: fused QKV projection.  Each block: 16 rows x 128 outputs, W streams
// from L2 (64KB x3, fully resident), input rows staged in smem (broadcast reads).
// ---------------------------------------------------------------------------
__global__ __launch_bounds__(128) void qkv_proj_kernel(
    const float* __restrict__ x,
    const float* __restrict__ Wq, const float* __restrict__ bq,
    const float* __restrict__ Wk, const float* __restrict__ bk,
    const float* __restrict__ Wv, const float* __restrict__ bv)
{
    __shared__ float sx[16 * DIM];
    const int d    = threadIdx.x;
    const int base = blockIdx.x * 16;

    #pragma unroll
    for (int r = 0; r < 16; ++r)
        sx[r * DIM + d] = x[(base + r) * DIM + d];
    __syncthreads();

    float aq[16], ak[16], av[16];
    const float q0 = bq[d], k0 = bk[d], v0 = bv[d];
    #pragma unroll
    for (int r = 0; r < 16; ++r) { aq[r] = q0; ak[r] = k0; av[r] = v0; }

    #pragma unroll 4
    for (int kk = 0; kk < DIM; ++kk) {
        const float wq = Wq[kk * DIM + d];
        const float wk = Wk[kk * DIM + d];
        const float wv = Wv[kk * DIM + d];
        #pragma unroll
        for (int r = 0; r < 16; ++r) {
            const float xv = sx[r * DIM + kk];
            aq[r] = fmaf(xv, wq, aq[r]);
            ak[r] = fmaf(xv, wk, ak[r]);
            av[r] = fmaf(xv, wv, av[r]);
        }
    }

    #pragma unroll
    for (int r = 0; r < 16; ++r) {
        g_q[(base + r) * DIM + d] = aq[r];
        g_k[(base + r) * DIM + d] = ak[r];
        g_v[(base + r) * DIM + d] = av[r];
    }
}

// ---------------------------------------------------------------------------
// Kernel 2: flash attention (online softmax) + additive adjacency bias + ELU.
// Grid (SEQ/BR, BATCH) = (16, 8) CTAs, 256 threads.
//
// smem (floats):
//   Qs  [0      .. 16383]  128x128, XOR-swizzled float4 columns
//   Ks  [16384  .. 24575]   64x128, XOR-swizzled float4 columns
//   Vs  [24576  .. 32767]   64x128, plain
//   Ss  [32768  .. 41087]  128x65 score/prob buffer (stride 65 kills conflicts)
//   alphas [41088..41215], lrow [41216..41343], mrow [41344..41471]
// total 41472 floats = 165888 bytes
// ---------------------------------------------------------------------------
constexpr int SMEM_FLOATS = 41472;
constexpr int SMEM_BYTES  = SMEM_FLOATS * 4;

__device__ __forceinline__ float elu1(float x) {
    return x > 0.0f ? x : expm1f(x);
}

__global__ __launch_bounds__(256, 1) void attn_kernel(
    const int* __restrict__ adj, float* __restrict__ out)
{
    extern __shared__ float sm[];
    float4* const Qs4    = (float4*)(sm);
    float4* const Ks4    = (float4*)(sm + 16384);
    float4* const Vs4    = (float4*)(sm + 24576);
    float*  const Ss     = sm + 32768;   // stride 65
    float*  const alphas = sm + 41088;
    float*  const lrow   = sm + 41216;
    float*  const mrow   = sm + 41344;

    const int t    = threadIdx.x;
    const int b    = blockIdx.y;
    const int row0 = blockIdx.x * BR;

    if (t < BR) { mrow[t] = -INFINITY; lrow[t] = 0.0f; }

    // ---- load Q tile once, XOR-swizzled on float4 columns ----
    {
        const float4* qg = (const float4*)(g_q + (size_t)(b * SEQ + row0) * DIM);
        #pragma unroll
        for (int i = 0; i < 16; ++i) {
            const int f  = i * 256 + t;      // 0..4095
            const int r  = f >> 5;
            const int c4 = f & 31;
            Qs4[r * 32 + (c4 ^ ((r >> 2) & 7))] = qg[f];
        }
    }

    // PV / output mapping: rows rg2*8+ri, cols {cg*4..+3} and {64+cg*4..+3}
    const int rg2 = t >> 4;   // 0..15
    const int cg  = t & 15;   // 0..15
    float o[8][8];
    #pragma unroll
    for (int ri = 0; ri < 8; ++ri)
        #pragma unroll
        for (int ci = 0; ci < 8; ++ci) o[ri][ci] = 0.0f;

    // score-phase mapping: rows rg*4+ri, keys kg*8+ji
    const int kg = t & 7;     // 0..7
    const int rg = t >> 3;    // 0..31

    for (int key0 = 0; key0 < SEQ; key0 += BC) {
        __syncthreads();   // previous chunk's Ss/Ks/Vs reads complete

        // ---- load K (swizzled) + V (plain) chunk ----
        {
            const float4* kgm = (const float4*)(g_k + (size_t)(b * SEQ + key0) * DIM);
            const float4* vgm = (const float4*)(g_v + (size_t)(b * SEQ + key0) * DIM);
            #pragma unroll
            for (int i = 0; i < 8; ++i) {
                const int f  = i * 256 + t;   // 0..2047
                const int r  = f >> 5;
                const int c4 = f & 31;
                Ks4[r * 32 + (c4 ^ ((r >> 3) & 7))] = kgm[f];
                Vs4[f] = vgm[f];
            }
        }
        __syncthreads();

        // ---- S = (Q K^T) * scale + bias ----
        {
            float acc[4][8];
            #pragma unroll
            for (int ri = 0; ri < 4; ++ri)
                #pragma unroll
                for (int ji = 0; ji < 8; ++ji) acc[ri][ji] = 0.0f;

            const int qsw = rg & 7;
            #pragma unroll 2
            for (int dd4 = 0; dd4 < 32; ++dd4) {
                float4 q4[4];
                #pragma unroll
                for (int ri = 0; ri < 4; ++ri)
                    q4[ri] = Qs4[(rg * 4 + ri) * 32 + (dd4 ^ qsw)];
                #pragma unroll
                for (int ji = 0; ji < 8; ++ji) {
                    const float4 k4 = Ks4[(kg * 8 + ji) * 32 + (dd4 ^ kg)];
                    #pragma unroll
                    for (int ri = 0; ri < 4; ++ri) {
                        acc[ri][ji] = fmaf(q4[ri].x, k4.x, acc[ri][ji]);
                        acc[ri][ji] = fmaf(q4[ri].y, k4.y, acc[ri][ji]);
                        acc[ri][ji] = fmaf(q4[ri].z, k4.z, acc[ri][ji]);
                        acc[ri][ji] = fmaf(q4[ri].w, k4.w, acc[ri][ji]);
                    }
                }
            }

            // adjacency bias (coalesced int4 loads straight from gmem) + store S
            #pragma unroll
            for (int ri = 0; ri < 4; ++ri) {
                const int r = rg * 4 + ri;
                const int4* ap =
                    (const int4*)(adj + ((size_t)b * SEQ + row0 + r) * SEQ + key0 + kg * 8);
                const int4 a0 = ap[0];
                const int4 a1 = ap[1];
                int am[8] = {a0.x, a0.y, a0.z, a0.w, a1.x, a1.y, a1.z, a1.w};
                float* srow = Ss + r * 65 + kg * 8;
                #pragma unroll
                for (int ji = 0; ji < 8; ++ji)
                    srow[ji] = fmaf(acc[ri][ji], SCALE, am[ji] ? 0.0f : NEG_BIG);
            }
        }
        __syncthreads();

        // ---- online softmax over this chunk (one thread per row) ----
        if (t < BR) {
            const int r = t;
            float* srow = Ss + r * 65;
            const float m_old = mrow[r];
            float mx = m_old;
            #pragma unroll 8
            for (int j = 0; j < BC; ++j) mx = fmaxf(mx, srow[j]);
            const float alpha = __expf(m_old - mx);
            float ls = 0.0f;
            #pragma unroll 8
            for (int j = 0; j < BC; ++j) {
                const float p = __expf(srow[j] - mx);
                srow[j] = p;
                ls += p;
            }
            mrow[r]   = mx;
            lrow[r]   = lrow[r] * alpha + ls;
            alphas[r] = alpha;
        }
        __syncthreads();

        // ---- O = O*alpha + P V ----
        {
            #pragma unroll
            for (int ri = 0; ri < 8; ++ri) {
                const float al = alphas[rg2 * 8 + ri];
                #pragma unroll
                for (int ci = 0; ci < 8; ++ci) o[ri][ci] *= al;
            }
            #pragma unroll 2
            for (int j = 0; j < BC; ++j) {
                const float4 vlo = Vs4[j * 32 + cg];
                const float4 vhi = Vs4[j * 32 + 16 + cg];
                #pragma unroll
                for (int ri = 0; ri < 8; ++ri) {
                    const float p = Ss[(rg2 * 8 + ri) * 65 + j];
                    o[ri][0] = fmaf(p, vlo.x, o[ri][0]);
                    o[ri][1] = fmaf(p, vlo.y, o[ri][1]);
                    o[ri][2] = fmaf(p, vlo.z, o[ri][2]);
                    o[ri][3] = fmaf(p, vlo.w, o[ri][3]);
                    o[ri][4] = fmaf(p, vhi.x, o[ri][4]);
                    o[ri][5] = fmaf(p, vhi.y, o[ri][5]);
                    o[ri][6] = fmaf(p, vhi.z, o[ri][6]);
                    o[ri][7] = fmaf(p, vhi.w, o[ri][7]);
                }
            }
        }
    }

    // ---- epilogue: normalize by l, ELU, coalesced float4 stores ----
    {
        float4* outp = (float4*)out;
        #pragma unroll
        for (int ri = 0; ri < 8; ++ri) {
            const int r = rg2 * 8 + ri;
            const float linv = 1.0f / lrow[r];
            float4 lo, hi;
            lo.x = elu1(o[ri][0] * linv);
            lo.y = elu1(o[ri][1] * linv);
            lo.z = elu1(o[ri][2] * linv);
            lo.w = elu1(o[ri][3] * linv);
            hi.x = elu1(o[ri][4] * linv);
            hi.y = elu1(o[ri][5] * linv);
            hi.z = elu1(o[ri][6] * linv);
            hi.w = elu1(o[ri][7] * linv);
            const size_t base4 = ((size_t)b * SEQ + row0 + r) * (DIM / 4);
            outp[base4 + cg]      = lo;
            outp[base4 + 16 + cg] = hi;
        }
    }
}

// ---------------------------------------------------------------------------
// Launch: projection then flash attention.  Graph-capturable: kernel launches
// + one (immediate, non-stream) func-attribute call; no allocs, no syncs.
// ---------------------------------------------------------------------------
extern "C" void kernel_launch(void* const* d_in, const int* in_sizes, int n_in,
                              void* d_out, int out_size)
{
    const float* x   = (const float*)d_in[0];
    const int*   adj = (const int*)  d_in[1];
    const float* Wq  = (const float*)d_in[2];
    const float* bq  = (const float*)d_in[3];
    const float* Wk  = (const float*)d_in[4];
    const float* bk  = (const float*)d_in[5];
    const float* Wv  = (const float*)d_in[6];
    const float* bv  = (const float*)d_in[7];
    float* out = (float*)d_out;

    qkv_proj_kernel<<<(BATCH * SEQ) / 16, 128>>>(x, Wq, bq, Wk, bk, Wv, bv);

    cudaFuncSetAttribute(attn_kernel,
                         cudaFuncAttributeMaxDynamicSharedMemorySize, SMEM_BYTES);
    attn_kernel<<<dim3(SEQ / BR, BATCH), 256, SMEM_BYTES>>>(adj, out);
}

// round 4
// speedup vs baseline: 1.8628x; 1.8628x over previous
#include <cuda_runtime.h>
#include <math.h>

// Problem constants
constexpr int BATCH = 8;
constexpr int SEQ   = 2048;
constexpr int DIM   = 128;
constexpr int BR    = 128;   // query rows per CTA
constexpr int BC    = 64;    // keys per chunk
constexpr float NEG_BIG = -10000.0f;
constexpr float SCALE   = 0.0883883476483184405f; // 1/sqrt(128)

// Scratch for Q,K,V projections (stored pre-rounded to tf32)
__device__ float g_q[BATCH * SEQ * DIM];
__device__ float g_k[BATCH * SEQ * DIM];
__device__ float g_v[BATCH * SEQ * DIM];

__device__ __forceinline__ float to_tf32(float x) {
    unsigned u;
    asm("cvt.rna.tf32.f32 %0, %1;" : "=r"(u) : "f"(x));
    return __uint_as_float(u);
}

// ---------------------------------------------------------------------------
// Kernel 1: fused QKV projection (fp32 FFMA), outputs rounded to tf32.
// ---------------------------------------------------------------------------
__global__ __launch_bounds__(128) void qkv_proj_kernel(
    const float* __restrict__ x,
    const float* __restrict__ Wq, const float* __restrict__ bq,
    const float* __restrict__ Wk, const float* __restrict__ bk,
    const float* __restrict__ Wv, const float* __restrict__ bv)
{
    __shared__ float sx[16 * DIM];
    const int d    = threadIdx.x;
    const int base = blockIdx.x * 16;

    #pragma unroll
    for (int r = 0; r < 16; ++r)
        sx[r * DIM + d] = x[(size_t)(base + r) * DIM + d];
    __syncthreads();

    float aq[16], ak[16], av[16];
    const float q0 = bq[d], k0 = bk[d], v0 = bv[d];
    #pragma unroll
    for (int r = 0; r < 16; ++r) { aq[r] = q0; ak[r] = k0; av[r] = v0; }

    #pragma unroll 4
    for (int kk = 0; kk < DIM; ++kk) {
        const float wq = Wq[kk * DIM + d];
        const float wk = Wk[kk * DIM + d];
        const float wv = Wv[kk * DIM + d];
        #pragma unroll
        for (int r = 0; r < 16; ++r) {
            const float xv = sx[r * DIM + kk];
            aq[r] = fmaf(xv, wq, aq[r]);
            ak[r] = fmaf(xv, wk, ak[r]);
            av[r] = fmaf(xv, wv, av[r]);
        }
    }

    #pragma unroll
    for (int r = 0; r < 16; ++r) {
        g_q[(size_t)(base + r) * DIM + d] = to_tf32(aq[r]);
        g_k[(size_t)(base + r) * DIM + d] = to_tf32(ak[r]);
        g_v[(size_t)(base + r) * DIM + d] = to_tf32(av[r]);
    }
}

// ---------------------------------------------------------------------------
// m16n8k8 tf32 tensor-core mma (fp32 accumulate)
// ---------------------------------------------------------------------------
__device__ __forceinline__ void mma_tf32(float (&c)[4], const float (&a)[4],
                                         const float (&bf)[2])
{
    const unsigned* A = reinterpret_cast<const unsigned*>(a);
    const unsigned* B = reinterpret_cast<const unsigned*>(bf);
    asm volatile(
        "mma.sync.aligned.m16n8k8.row.col.f32.tf32.tf32.f32 "
        "{%0,%1,%2,%3}, {%4,%5,%6,%7}, {%8,%9}, {%0,%1,%2,%3};\n"
        : "+f"(c[0]), "+f"(c[1]), "+f"(c[2]), "+f"(c[3])
        : "r"(A[0]), "r"(A[1]), "r"(A[2]), "r"(A[3]), "r"(B[0]), "r"(B[1]));
}

__device__ __forceinline__ float elu1(float x) {
    return x > 0.0f ? x : expm1f(x);
}

// ---------------------------------------------------------------------------
// Kernel 2: tensor-core flash attention + adjacency bias + ELU.
// Grid (16, 8), 256 threads (8 warps). Warp w owns query rows 16w..16w+15.
//
// smem (floats):
//   Ks [64][132]  natural [key][d], stride 132 (conflict-free frag loads)
//   Vs [64][132]  natural [key][d]
//   Ps [128][68]  probabilities, stride 68
// ---------------------------------------------------------------------------
constexpr int KVSTRIDE = 132;
constexpr int PSTRIDE  = 68;
constexpr int KS_OFF = 0;
constexpr int VS_OFF = 64 * KVSTRIDE;            // 8448
constexpr int PS_OFF = VS_OFF + 64 * KVSTRIDE;   // 16896
constexpr int SMEM_FLOATS = PS_OFF + BR * PSTRIDE;  // 16896 + 8704 = 25600
constexpr int SMEM_BYTES  = SMEM_FLOATS * 4;        // 102400

__global__ __launch_bounds__(256, 1) void attn_kernel(
    const int* __restrict__ adj, float* __restrict__ out)
{
    extern __shared__ float sm[];
    float* const Ks = sm + KS_OFF;
    float* const Vs = sm + VS_OFF;
    float* const Ps = sm + PS_OFF;

    const int t    = threadIdx.x;
    const int w    = t >> 5;
    const int lane = t & 31;
    const int qr   = lane >> 2;   // fragment row within tile (0..7)
    const int qc   = lane & 3;    // fragment col group (0..3)
    const int b    = blockIdx.y;
    const int row0 = blockIdx.x * BR;

    // ---- Q fragments in registers for the whole kernel ----
    float Qf[16][4];
    {
        const float* qb = g_q + (size_t)(b * SEQ + row0 + 16 * w) * DIM;
        #pragma unroll
        for (int kt = 0; kt < 16; ++kt) {
            const int c0 = 8 * kt + qc;
            Qf[kt][0] = qb[(size_t)qr * DIM + c0];
            Qf[kt][1] = qb[(size_t)(qr + 8) * DIM + c0];
            Qf[kt][2] = qb[(size_t)qr * DIM + c0 + 4];
            Qf[kt][3] = qb[(size_t)(qr + 8) * DIM + c0 + 4];
        }
    }

    float O[16][4];
    #pragma unroll
    for (int j = 0; j < 16; ++j)
        #pragma unroll
        for (int i = 0; i < 4; ++i) O[j][i] = 0.0f;

    float m0 = -INFINITY, m1 = -INFINITY, l0 = 0.0f, l1 = 0.0f;

    const int r0g = row0 + 16 * w + qr;       // global rows this thread owns
    const int r1g = r0g + 8;
    const int* adj0 = adj + ((size_t)b * SEQ + r0g) * SEQ;
    const int* adj1 = adj + ((size_t)b * SEQ + r1g) * SEQ;

    for (int key0 = 0; key0 < SEQ; key0 += BC) {
        __syncthreads();   // previous chunk's Ks/Vs reads done

        // ---- load K,V chunk (coalesced float4, conflict-free STS) ----
        {
            const float4* kg = (const float4*)(g_k + (size_t)(b * SEQ + key0) * DIM);
            const float4* vg = (const float4*)(g_v + (size_t)(b * SEQ + key0) * DIM);
            #pragma unroll
            for (int i = 0; i < 8; ++i) {
                const int f   = i * 256 + t;   // 0..2047
                const int key = f >> 5;
                const int c4  = f & 31;
                *(float4*)(Ks + key * KVSTRIDE + 4 * c4) = kg[f];
                *(float4*)(Vs + key * KVSTRIDE + 4 * c4) = vg[f];
            }
        }
        __syncthreads();

        // ---- S = Q K^T via tensor cores ----
        float Sacc[8][4];
        #pragma unroll
        for (int j = 0; j < 8; ++j)
            #pragma unroll
            for (int i = 0; i < 4; ++i) Sacc[j][i] = 0.0f;

        #pragma unroll
        for (int kt = 0; kt < 16; ++kt) {
            #pragma unroll
            for (int jn = 0; jn < 8; ++jn) {
                float bf[2];
                const float* kp = Ks + (8 * jn + qr) * KVSTRIDE + 8 * kt + qc;
                bf[0] = kp[0];
                bf[1] = kp[4];
                mma_tf32(Sacc[jn], Qf[kt], bf);
            }
        }

        // ---- scale + adjacency bias (registers) ----
        float p[8][4];
        float mx0 = -INFINITY, mx1 = -INFINITY;
        #pragma unroll
        for (int jn = 0; jn < 8; ++jn) {
            const int col = key0 + 8 * jn + 2 * qc;
            const int2 a0 = *(const int2*)(adj0 + col);
            const int2 a1 = *(const int2*)(adj1 + col);
            p[jn][0] = fmaf(Sacc[jn][0], SCALE, a0.x ? 0.0f : NEG_BIG);
            p[jn][1] = fmaf(Sacc[jn][1], SCALE, a0.y ? 0.0f : NEG_BIG);
            p[jn][2] = fmaf(Sacc[jn][2], SCALE, a1.x ? 0.0f : NEG_BIG);
            p[jn][3] = fmaf(Sacc[jn][3], SCALE, a1.y ? 0.0f : NEG_BIG);
            mx0 = fmaxf(mx0, fmaxf(p[jn][0], p[jn][1]));
            mx1 = fmaxf(mx1, fmaxf(p[jn][2], p[jn][3]));
        }
        // quad reduction: row is spread over 4 lanes (xor 1, 2)
        mx0 = fmaxf(mx0, __shfl_xor_sync(0xffffffffu, mx0, 1));
        mx0 = fmaxf(mx0, __shfl_xor_sync(0xffffffffu, mx0, 2));
        mx1 = fmaxf(mx1, __shfl_xor_sync(0xffffffffu, mx1, 1));
        mx1 = fmaxf(mx1, __shfl_xor_sync(0xffffffffu, mx1, 2));

        const float mn0 = fmaxf(m0, mx0);
        const float mn1 = fmaxf(m1, mx1);
        const float alpha0 = __expf(m0 - mn0);
        const float alpha1 = __expf(m1 - mn1);
        m0 = mn0; m1 = mn1;

        float sum0 = 0.0f, sum1 = 0.0f;
        #pragma unroll
        for (int jn = 0; jn < 8; ++jn) {
            p[jn][0] = __expf(p[jn][0] - mn0);
            p[jn][1] = __expf(p[jn][1] - mn0);
            p[jn][2] = __expf(p[jn][2] - mn1);
            p[jn][3] = __expf(p[jn][3] - mn1);
            sum0 += p[jn][0] + p[jn][1];
            sum1 += p[jn][2] + p[jn][3];
            // store P (tf32-rounded) to warp-private smem rows
            float2* d0 = (float2*)(Ps + (16 * w + qr) * PSTRIDE + 8 * jn + 2 * qc);
            float2* d1 = (float2*)(Ps + (16 * w + qr + 8) * PSTRIDE + 8 * jn + 2 * qc);
            *d0 = make_float2(to_tf32(p[jn][0]), to_tf32(p[jn][1]));
            *d1 = make_float2(to_tf32(p[jn][2]), to_tf32(p[jn][3]));
        }
        sum0 += __shfl_xor_sync(0xffffffffu, sum0, 1);
        sum0 += __shfl_xor_sync(0xffffffffu, sum0, 2);
        sum1 += __shfl_xor_sync(0xffffffffu, sum1, 1);
        sum1 += __shfl_xor_sync(0xffffffffu, sum1, 2);
        l0 = l0 * alpha0 + sum0;
        l1 = l1 * alpha1 + sum1;

        // rescale O
        #pragma unroll
        for (int jn = 0; jn < 16; ++jn) {
            O[jn][0] *= alpha0; O[jn][1] *= alpha0;
            O[jn][2] *= alpha1; O[jn][3] *= alpha1;
        }

        __syncwarp();   // P fragment redistribution is warp-local

        // ---- O += P V via tensor cores ----
        #pragma unroll
        for (int kk = 0; kk < 8; ++kk) {
            float af[4];
            const float* pp = Ps + (16 * w + qr) * PSTRIDE + 8 * kk + qc;
            af[0] = pp[0];
            af[1] = pp[8 * PSTRIDE];
            af[2] = pp[4];
            af[3] = pp[8 * PSTRIDE + 4];
            #pragma unroll
            for (int jn = 0; jn < 16; ++jn) {
                float bf[2];
                const float* vp = Vs + (8 * kk + qc) * KVSTRIDE + 8 * jn + qr;
                bf[0] = vp[0];
                bf[1] = vp[4 * KVSTRIDE];
                mma_tf32(O[jn], af, bf);
            }
        }
        __syncwarp();   // Ps reads done before next chunk overwrites (warp-local)
    }

    // ---- epilogue: normalize, ELU, store ----
    {
        const float li0 = 1.0f / l0;
        const float li1 = 1.0f / l1;
        float* out0 = out + ((size_t)b * SEQ + r0g) * DIM;
        float* out1 = out + ((size_t)b * SEQ + r1g) * DIM;
        #pragma unroll
        for (int jn = 0; jn < 16; ++jn) {
            const int col = 8 * jn + 2 * qc;
            *(float2*)(out0 + col) =
                make_float2(elu1(O[jn][0] * li0), elu1(O[jn][1] * li0));
            *(float2*)(out1 + col) =
                make_float2(elu1(O[jn][2] * li1), elu1(O[jn][3] * li1));
        }
    }
}

// ---------------------------------------------------------------------------
extern "C" void kernel_launch(void* const* d_in, const int* in_sizes, int n_in,
                              void* d_out, int out_size)
{
    const float* x   = (const float*)d_in[0];
    const int*   adj = (const int*)  d_in[1];
    const float* Wq  = (const float*)d_in[2];
    const float* bq  = (const float*)d_in[3];
    const float* Wk  = (const float*)d_in[4];
    const float* bk  = (const float*)d_in[5];
    const float* Wv  = (const float*)d_in[6];
    const float* bv  = (const float*)d_in[7];
    float* out = (float*)d_out;

    qkv_proj_kernel<<<(BATCH * SEQ) / 16, 128>>>(x, Wq, bq, Wk, bk, Wv, bv);

    cudaFuncSetAttribute(attn_kernel,
                         cudaFuncAttributeMaxDynamicSharedMemorySize, SMEM_BYTES);
    attn_kernel<<<dim3(SEQ / BR, BATCH), 256, SMEM_BYTES>>>(adj, out);
}

// round 6
// speedup vs baseline: 1.9550x; 1.0495x over previous
#include <cuda_runtime.h>
#include <math.h>

// Problem constants
constexpr int BATCH = 8;
constexpr int SEQ   = 2048;
constexpr int DIM   = 128;
constexpr int BR    = 128;   // query rows per CTA
constexpr int BC    = 64;    // keys per chunk
constexpr int NCHUNK = SEQ / BC;
constexpr float NEG_BIG = -10000.0f;
constexpr float SCALE   = 0.0883883476483184405f; // 1/sqrt(128)

// Scratch: projections (tf32-rounded). V is stored TRANSPOSED: g_vt[b][d][seq].
__device__ float g_q [BATCH * SEQ * DIM];
__device__ float g_k [BATCH * SEQ * DIM];
__device__ float g_vt[BATCH * DIM * SEQ];

__device__ __forceinline__ float to_tf32(float x) {
    unsigned u;
    asm("cvt.rna.tf32.f32 %0, %1;" : "=r"(u) : "f"(x));
    return __uint_as_float(u);
}

// m16n8k8 tf32 tensor-core mma (fp32 accumulate)
__device__ __forceinline__ void mma_tf32(float (&c)[4], const float (&a)[4],
                                         const float (&bf)[2])
{
    const unsigned* A = reinterpret_cast<const unsigned*>(a);
    const unsigned* B = reinterpret_cast<const unsigned*>(bf);
    asm volatile(
        "mma.sync.aligned.m16n8k8.row.col.f32.tf32.tf32.f32 "
        "{%0,%1,%2,%3}, {%4,%5,%6,%7}, {%8,%9}, {%0,%1,%2,%3};\n"
        : "+f"(c[0]), "+f"(c[1]), "+f"(c[2]), "+f"(c[3])
        : "r"(A[0]), "r"(A[1]), "r"(A[2]), "r"(A[3]), "r"(B[0]), "r"(B[1]));
}

__device__ __forceinline__ float elu1(float x) {
    return x > 0.0f ? x : expm1f(x);
}

// ===========================================================================
// Kernel 1: QKV projection on tensor cores.  grid = (rows/128, 3).
// blockIdx.y: 0 -> Q, 1 -> K, 2 -> V-transposed.
// smem: Xs[128][132] + Ws[128][132]
// ===========================================================================
constexpr int PSM_FLOATS = 2 * 128 * 132;
constexpr int PSM_BYTES  = PSM_FLOATS * 4;

__global__ __launch_bounds__(256) void proj_kernel(
    const float* __restrict__ x,
    const float* __restrict__ Wq, const float* __restrict__ bq,
    const float* __restrict__ Wk, const float* __restrict__ bk,
    const float* __restrict__ Wv, const float* __restrict__ bv)
{
    extern __shared__ float psm[];
    float* const Xs = psm;
    float* const Ws = psm + 128 * 132;

    const int t    = threadIdx.x;
    const int w    = t >> 5;
    const int lane = t & 31;
    const int qr   = lane >> 2;
    const int qc   = lane & 3;
    const int gy   = blockIdx.y;
    const int row0 = blockIdx.x * 128;

    const float* W    = gy == 0 ? Wq : (gy == 1 ? Wk : Wv);
    const float* bias = gy == 0 ? bq : (gy == 1 ? bk : bv);

    const float4* xg = (const float4*)(x + (size_t)row0 * DIM);
    const float4* wg = (const float4*)W;
    #pragma unroll
    for (int i = 0; i < 16; ++i) {
        const int f = i * 256 + t;           // 0..4095
        const int r = f >> 5, c4 = f & 31;
        *(float4*)(Xs + r * 132 + 4 * c4) = xg[f];
        *(float4*)(Ws + r * 132 + 4 * c4) = wg[f];
    }
    __syncthreads();

    float C[16][4];
    #pragma unroll
    for (int n = 0; n < 16; ++n)
        #pragma unroll
        for (int i = 0; i < 4; ++i) C[n][i] = 0.0f;

    #pragma unroll
    for (int kt = 0; kt < 16; ++kt) {
        float a[4];
        const float* ap = Xs + (16 * w + qr) * 132 + 8 * kt + qc;
        a[0] = ap[0];
        a[1] = ap[8 * 132];
        a[2] = ap[4];
        a[3] = ap[8 * 132 + 4];
        #pragma unroll
        for (int n = 0; n < 16; ++n) {
            float bf[2];
            const float* bp = Ws + (8 * kt + qc) * 132 + 8 * n + qr;
            bf[0] = bp[0];
            bf[1] = bp[4 * 132];
            mma_tf32(C[n], a, bf);
        }
    }

    const int r0 = row0 + 16 * w + qr;     // global row (0..16383)
    if (gy < 2) {
        float* dst = (gy == 0 ? g_q : g_k) + (size_t)r0 * DIM;
        #pragma unroll
        for (int n = 0; n < 16; ++n) {
            const int c0 = 8 * n + 2 * qc;
            const float b0 = bias[c0], b1 = bias[c0 + 1];
            *(float2*)(dst + c0) =
                make_float2(to_tf32(C[n][0] + b0), to_tf32(C[n][1] + b1));
            *(float2*)(dst + 8 * DIM + c0) =
                make_float2(to_tf32(C[n][2] + b0), to_tf32(C[n][3] + b1));
        }
    } else {
        const int bb = r0 >> 11;           // batch
        const int sr = r0 & 2047;          // seq pos
        float* base = g_vt + (size_t)bb * DIM * SEQ + sr;
        #pragma unroll
        for (int n = 0; n < 16; ++n) {
            const int d0 = 8 * n + 2 * qc;
            const float b0 = bias[d0], b1 = bias[d0 + 1];
            base[(size_t)d0 * SEQ]           = to_tf32(C[n][0] + b0);
            base[(size_t)(d0 + 1) * SEQ]     = to_tf32(C[n][1] + b1);
            base[(size_t)d0 * SEQ + 8]       = to_tf32(C[n][2] + b0);
            base[(size_t)(d0 + 1) * SEQ + 8] = to_tf32(C[n][3] + b1);
        }
    }
}

// ===========================================================================
// Kernel 2: tensor-core flash attention, fragment-major swizzled K/V smem,
// double-buffered chunks.  Grid (16, 8), 256 threads (8 warps, m16 each).
//
// K frag layout:  Kf[a:8][li:32][g:8] float4, phys offset for logical g is
//                 (g ^ (li&7)); float4 = {kt=2g:(b0,b1), kt=2g+1:(b0,b1)}.
// V frag layout:  Vf[a:16][li:32][g:4] float4, swizzle (g ^ ((li>>1)&3));
//                 float4 = {kk=2g:(b0,b1), kk=2g+1:(b0,b1)}.
// Both proven bank-conflict-free for LDS.128 reads and scalar STS writes.
// ===========================================================================
constexpr int KOFF0 = 0;        // 8192 floats each K buffer
constexpr int KOFF1 = 8192;
constexpr int VOFF0 = 16384;    // 8192 floats each V buffer
constexpr int VOFF1 = 24576;
constexpr int PSOFF = 32768;    // Ps[128][68]
constexpr int PSTRIDE = 68;
constexpr int SMEM_FLOATS = PSOFF + BR * PSTRIDE;   // 41472
constexpr int SMEM_BYTES  = SMEM_FLOATS * 4;        // 165888

__device__ __forceinline__ void ldg_k(float4 (&r)[8], const float4* kg, int t) {
    #pragma unroll
    for (int i = 0; i < 8; ++i) r[i] = kg[i * 256 + t];
}
__device__ __forceinline__ void sts_k(float* Kf, const float4 (&r)[8], int t) {
    #pragma unroll
    for (int i = 0; i < 8; ++i) {
        const int f   = i * 256 + t;
        const int key = f >> 5, c4 = f & 31;
        float* blk = Kf + (key >> 3) * 1024;
        const int lib = (key & 7) * 4;
        const float* v = &r[i].x;
        #pragma unroll
        for (int e = 0; e < 4; ++e) {
            const int li = lib + e;
            blk[li * 32 + (((c4 >> 2) ^ (li & 7)) << 2) + (c4 & 3)] = v[e];
        }
    }
}
__device__ __forceinline__ void ldg_v(float4 (&r)[8], const float* vtb,
                                      int key0, int t) {
    #pragma unroll
    for (int i = 0; i < 8; ++i) {
        const int f = i * 256 + t;
        const int d = f >> 4, c4 = f & 15;
        r[i] = *(const float4*)(vtb + (size_t)d * SEQ + key0 + 4 * c4);
    }
}
__device__ __forceinline__ void sts_v(float* Vf, const float4 (&r)[8], int t) {
    #pragma unroll
    for (int i = 0; i < 8; ++i) {
        const int f = i * 256 + t;
        const int d = f >> 4, c4 = f & 15;
        float* blk = Vf + (d >> 3) * 512;
        const int lib = (d & 7) * 4;
        const float* v = &r[i].x;
        #pragma unroll
        for (int e = 0; e < 4; ++e) {
            const int li = lib + e;
            const int s  = (li >> 1) & 3;
            blk[li * 16 + (((c4 >> 2) ^ s) << 2) + (c4 & 3)] = v[e];
        }
    }
}

__global__ __launch_bounds__(256, 1) void attn_kernel(
    const int* __restrict__ adj, float* __restrict__ out)
{
    extern __shared__ float sm[];
    float* const Ps = sm + PSOFF;

    const int t    = threadIdx.x;
    const int w    = t >> 5;
    const int lane = t & 31;
    const int qr   = lane >> 2;
    const int qc   = lane & 3;
    const int b    = blockIdx.y;
    const int row0 = blockIdx.x * BR;

    // ---- Q fragments in registers for the whole kernel ----
    float Qf[16][4];
    {
        const float* qb = g_q + (size_t)(b * SEQ + row0 + 16 * w) * DIM;
        #pragma unroll
        for (int kt = 0; kt < 16; ++kt) {
            const int c0 = 8 * kt + qc;
            Qf[kt][0] = qb[(size_t)qr * DIM + c0];
            Qf[kt][1] = qb[(size_t)(qr + 8) * DIM + c0];
            Qf[kt][2] = qb[(size_t)qr * DIM + c0 + 4];
            Qf[kt][3] = qb[(size_t)(qr + 8) * DIM + c0 + 4];
        }
    }

    float O[16][4];
    #pragma unroll
    for (int j = 0; j < 16; ++j)
        #pragma unroll
        for (int i = 0; i < 4; ++i) O[j][i] = 0.0f;

    float m0 = -INFINITY, m1 = -INFINITY, l0 = 0.0f, l1 = 0.0f;

    const int r0g = row0 + 16 * w + qr;
    const int r1g = r0g + 8;
    const int* adj0 = adj + ((size_t)b * SEQ + r0g) * SEQ;
    const int* adj1 = adj + ((size_t)b * SEQ + r1g) * SEQ;

    const float*  kbase  = g_k + (size_t)b * SEQ * DIM;
    const float*  vtbase = g_vt + (size_t)b * DIM * SEQ;

    float4 kreg[8], vreg[8];

    // preload chunk 0
    ldg_k(kreg, (const float4*)kbase, t);
    ldg_v(vreg, vtbase, 0, t);
    sts_k(sm + KOFF0, kreg, t);
    sts_v(sm + VOFF0, vreg, t);
    __syncthreads();

    for (int c = 0; c < NCHUNK; ++c) {
        float* const Kc = sm + ((c & 1) ? KOFF1 : KOFF0);
        float* const Vc = sm + ((c & 1) ? VOFF1 : VOFF0);
        float* const Kn = sm + ((c & 1) ? KOFF0 : KOFF1);
        float* const Vn = sm + ((c & 1) ? VOFF0 : VOFF1);
        const int key0 = c * BC;
        const bool pf  = (c + 1 < NCHUNK);

        // prefetch next V (latency hidden under QK mma)
        if (pf) ldg_v(vreg, vtbase, key0 + BC, t);

        // ---- S = Q K^T ----
        float Sacc[8][4];
        #pragma unroll
        for (int j = 0; j < 8; ++j)
            #pragma unroll
            for (int i = 0; i < 4; ++i) Sacc[j][i] = 0.0f;

        #pragma unroll
        for (int a = 0; a < 8; ++a) {
            const float* kb = Kc + a * 1024 + lane * 32;
            #pragma unroll
            for (int g = 0; g < 8; ++g) {
                const float4 kf = *(const float4*)(kb + ((g ^ (lane & 7)) << 2));
                float bf0[2] = {kf.x, kf.y};
                float bf1[2] = {kf.z, kf.w};
                mma_tf32(Sacc[a], Qf[2 * g],     bf0);
                mma_tf32(Sacc[a], Qf[2 * g + 1], bf1);
            }
        }

        if (pf) { sts_v(Vn, vreg, t); ldg_k(kreg, (const float4*)(kbase + (size_t)(key0 + BC) * DIM), t); }

        // ---- scale + adjacency bias ----
        float p[8][4];
        float mx0 = -INFINITY, mx1 = -INFINITY;
        #pragma unroll
        for (int jn = 0; jn < 8; ++jn) {
            const int col = key0 + 8 * jn + 2 * qc;
            const int2 a0 = *(const int2*)(adj0 + col);
            const int2 a1 = *(const int2*)(adj1 + col);
            p[jn][0] = fmaf(Sacc[jn][0], SCALE, a0.x ? 0.0f : NEG_BIG);
            p[jn][1] = fmaf(Sacc[jn][1], SCALE, a0.y ? 0.0f : NEG_BIG);
            p[jn][2] = fmaf(Sacc[jn][2], SCALE, a1.x ? 0.0f : NEG_BIG);
            p[jn][3] = fmaf(Sacc[jn][3], SCALE, a1.y ? 0.0f : NEG_BIG);
            mx0 = fmaxf(mx0, fmaxf(p[jn][0], p[jn][1]));
            mx1 = fmaxf(mx1, fmaxf(p[jn][2], p[jn][3]));
        }
        mx0 = fmaxf(mx0, __shfl_xor_sync(0xffffffffu, mx0, 1));
        mx0 = fmaxf(mx0, __shfl_xor_sync(0xffffffffu, mx0, 2));
        mx1 = fmaxf(mx1, __shfl_xor_sync(0xffffffffu, mx1, 1));
        mx1 = fmaxf(mx1, __shfl_xor_sync(0xffffffffu, mx1, 2));

        const float mn0 = fmaxf(m0, mx0);
        const float mn1 = fmaxf(m1, mx1);
        const float alpha0 = __expf(m0 - mn0);
        const float alpha1 = __expf(m1 - mn1);
        m0 = mn0; m1 = mn1;

        float sum0 = 0.0f, sum1 = 0.0f;
        #pragma unroll
        for (int jn = 0; jn < 8; ++jn) {
            p[jn][0] = __expf(p[jn][0] - mn0);
            p[jn][1] = __expf(p[jn][1] - mn0);
            p[jn][2] = __expf(p[jn][2] - mn1);
            p[jn][3] = __expf(p[jn][3] - mn1);
            sum0 += p[jn][0] + p[jn][1];
            sum1 += p[jn][2] + p[jn][3];
            float2* d0 = (float2*)(Ps + (16 * w + qr) * PSTRIDE + 8 * jn + 2 * qc);
            float2* d1 = (float2*)(Ps + (16 * w + qr + 8) * PSTRIDE + 8 * jn + 2 * qc);
            *d0 = make_float2(to_tf32(p[jn][0]), to_tf32(p[jn][1]));
            *d1 = make_float2(to_tf32(p[jn][2]), to_tf32(p[jn][3]));
        }
        sum0 += __shfl_xor_sync(0xffffffffu, sum0, 1);
        sum0 += __shfl_xor_sync(0xffffffffu, sum0, 2);
        sum1 += __shfl_xor_sync(0xffffffffu, sum1, 1);
        sum1 += __shfl_xor_sync(0xffffffffu, sum1, 2);
        l0 = l0 * alpha0 + sum0;
        l1 = l1 * alpha1 + sum1;

        #pragma unroll
        for (int jn = 0; jn < 16; ++jn) {
            O[jn][0] *= alpha0; O[jn][1] *= alpha0;
            O[jn][2] *= alpha1; O[jn][3] *= alpha1;
        }

        __syncwarp();   // P visible to quad-mates

        // ---- O += P V ----
        #pragma unroll
        for (int g = 0; g < 4; ++g) {     // key-block pair (2g, 2g+1)
            float a0[4], a1[4];
            const float* pp0 = Ps + (16 * w + qr) * PSTRIDE + 16 * g + qc;
            a0[0] = pp0[0];
            a0[1] = pp0[8 * PSTRIDE];
            a0[2] = pp0[4];
            a0[3] = pp0[8 * PSTRIDE + 4];
            a1[0] = pp0[8];
            a1[1] = pp0[8 * PSTRIDE + 8];
            a1[2] = pp0[12];
            a1[3] = pp0[8 * PSTRIDE + 12];
            const int sw = ((lane >> 1) & 3);
            #pragma unroll
            for (int a = 0; a < 16; ++a) {
                const float* vb = Vc + a * 512 + lane * 16;
                const float4 vf = *(const float4*)(vb + ((g ^ sw) << 2));
                float bf0[2] = {vf.x, vf.y};
                float bf1[2] = {vf.z, vf.w};
                mma_tf32(O[a], a0, bf0);
                mma_tf32(O[a], a1, bf1);
            }
        }
        __syncwarp();   // Ps reads done before next chunk rewrites

        if (pf) sts_k(Kn, kreg, t);
        __syncthreads();
    }

    // ---- epilogue: normalize, ELU, store ----
    {
        const float li0 = 1.0f / l0;
        const float li1 = 1.0f / l1;
        float* out0 = out + ((size_t)b * SEQ + r0g) * DIM;
        float* out1 = out + ((size_t)b * SEQ + r1g) * DIM;
        #pragma unroll
        for (int jn = 0; jn < 16; ++jn) {
            const int col = 8 * jn + 2 * qc;
            *(float2*)(out0 + col) =
                make_float2(elu1(O[jn][0] * li0), elu1(O[jn][1] * li0));
            *(float2*)(out1 + col) =
                make_float2(elu1(O[jn][2] * li1), elu1(O[jn][3] * li1));
        }
    }
}

// ---------------------------------------------------------------------------
extern "C" void kernel_launch(void* const* d_in, const int* in_sizes, int n_in,
                              void* d_out, int out_size)
{
    const float* x   = (const float*)d_in[0];
    const int*   adj = (const int*)  d_in[1];
    const float* Wq  = (const float*)d_in[2];
    const float* bq  = (const float*)d_in[3];
    const float* Wk  = (const float*)d_in[4];
    const float* bk  = (const float*)d_in[5];
    const float* Wv  = (const float*)d_in[6];
    const float* bv  = (const float*)d_in[7];
    float* out = (float*)d_out;

    cudaFuncSetAttribute(proj_kernel,
                         cudaFuncAttributeMaxDynamicSharedMemorySize, PSM_BYTES);
    cudaFuncSetAttribute(attn_kernel,
                         cudaFuncAttributeMaxDynamicSharedMemorySize, SMEM_BYTES);

    proj_kernel<<<dim3((BATCH * SEQ) / 128, 3), 256, PSM_BYTES>>>(
        x, Wq, bq, Wk, bk, Wv, bv);

    attn_kernel<<<dim3(SEQ / BR, BATCH), 256, SMEM_BYTES>>>(adj, out);
}

// round 7
// speedup vs baseline: 2.2211x; 1.1361x over previous
#include <cuda_runtime.h>
#include <math.h>

// Problem constants
constexpr int BATCH = 8;
constexpr int SEQ   = 2048;
constexpr int DIM   = 128;
constexpr int BR    = 64;    // query rows per CTA (2 CTAs / SM)
constexpr int BC    = 64;    // keys per chunk
constexpr int NCHUNK = SEQ / BC;
constexpr float NEG_BIG = -10000.0f;
constexpr float SCALE   = 0.0883883476483184405f; // 1/sqrt(128)

// Scratch: projections (tf32-rounded). V stored TRANSPOSED: g_vt[b][d][seq].
__device__ float g_q [BATCH * SEQ * DIM];
__device__ float g_k [BATCH * SEQ * DIM];
__device__ float g_vt[BATCH * DIM * SEQ];

__device__ __forceinline__ float to_tf32(float x) {
    unsigned u;
    asm("cvt.rna.tf32.f32 %0, %1;" : "=r"(u) : "f"(x));
    return __uint_as_float(u);
}

// m16n8k8 tf32 tensor-core mma (fp32 accumulate)
__device__ __forceinline__ void mma_tf32(float (&c)[4], const float (&a)[4],
                                         const float (&bf)[2])
{
    const unsigned* A = reinterpret_cast<const unsigned*>(a);
    const unsigned* B = reinterpret_cast<const unsigned*>(bf);
    asm volatile(
        "mma.sync.aligned.m16n8k8.row.col.f32.tf32.tf32.f32 "
        "{%0,%1,%2,%3}, {%4,%5,%6,%7}, {%8,%9}, {%0,%1,%2,%3};\n"
        : "+f"(c[0]), "+f"(c[1]), "+f"(c[2]), "+f"(c[3])
        : "r"(A[0]), "r"(A[1]), "r"(A[2]), "r"(A[3]), "r"(B[0]), "r"(B[1]));
}

__device__ __forceinline__ float elu1(float x) {
    return x > 0.0f ? x : expm1f(x);
}

// ===========================================================================
// Kernel 1: QKV projection, tf32 tensor cores with hi/lo split (fp32-quality).
// Grid = 128 CTAs (one 128-row tile each), 256 threads. Xs loaded once; the
// three weight matrices are cycled through Ws. Outputs rounded to tf32.
// ===========================================================================
constexpr int PSM_FLOATS = 2 * 128 * 132;
constexpr int PSM_BYTES  = PSM_FLOATS * 4;

__global__ __launch_bounds__(256) void proj_kernel(
    const float* __restrict__ x,
    const float* __restrict__ Wq, const float* __restrict__ bq,
    const float* __restrict__ Wk, const float* __restrict__ bk,
    const float* __restrict__ Wv, const float* __restrict__ bv)
{
    extern __shared__ float psm[];
    float* const Xs = psm;
    float* const Ws = psm + 128 * 132;

    const int t    = threadIdx.x;
    const int w    = t >> 5;
    const int lane = t & 31;
    const int qr   = lane >> 2;
    const int qc   = lane & 3;
    const int row0 = blockIdx.x * 128;

    // load X tile once
    {
        const float4* xg = (const float4*)(x + (size_t)row0 * DIM);
        #pragma unroll
        for (int i = 0; i < 16; ++i) {
            const int f = i * 256 + t;
            const int r = f >> 5, c4 = f & 31;
            *(float4*)(Xs + r * 132 + 4 * c4) = xg[f];
        }
    }

    #pragma unroll 1
    for (int gy = 0; gy < 3; ++gy) {
        const float* W    = gy == 0 ? Wq : (gy == 1 ? Wk : Wv);
        const float* bias = gy == 0 ? bq : (gy == 1 ? bk : bv);

        __syncthreads();   // previous Ws reads done
        {
            const float4* wg = (const float4*)W;
            #pragma unroll
            for (int i = 0; i < 16; ++i) {
                const int f = i * 256 + t;
                const int r = f >> 5, c4 = f & 31;
                *(float4*)(Ws + r * 132 + 4 * c4) = wg[f];
            }
        }
        __syncthreads();   // Ws (and, first pass, Xs) visible

        float C[16][4];
        #pragma unroll
        for (int n = 0; n < 16; ++n)
            #pragma unroll
            for (int i = 0; i < 4; ++i) C[n][i] = 0.0f;

        #pragma unroll
        for (int kt = 0; kt < 16; ++kt) {
            float ah[4], al[4];
            {
                const float* ap = Xs + (16 * w + qr) * 132 + 8 * kt + qc;
                float a0 = ap[0], a1 = ap[8 * 132], a2 = ap[4], a3 = ap[8 * 132 + 4];
                ah[0] = to_tf32(a0); al[0] = to_tf32(a0 - ah[0]);
                ah[1] = to_tf32(a1); al[1] = to_tf32(a1 - ah[1]);
                ah[2] = to_tf32(a2); al[2] = to_tf32(a2 - ah[2]);
                ah[3] = to_tf32(a3); al[3] = to_tf32(a3 - ah[3]);
            }
            #pragma unroll
            for (int n = 0; n < 16; ++n) {
                const float* bp = Ws + (8 * kt + qc) * 132 + 8 * n + qr;
                const float b0 = bp[0], b1 = bp[4 * 132];
                float bh[2], bl[2];
                bh[0] = to_tf32(b0); bl[0] = to_tf32(b0 - bh[0]);
                bh[1] = to_tf32(b1); bl[1] = to_tf32(b1 - bh[1]);
                mma_tf32(C[n], ah, bh);
                mma_tf32(C[n], al, bh);
                mma_tf32(C[n], ah, bl);
            }
        }

        const int r0 = row0 + 16 * w + qr;
        if (gy < 2) {
            float* dst = (gy == 0 ? g_q : g_k) + (size_t)r0 * DIM;
            #pragma unroll
            for (int n = 0; n < 16; ++n) {
                const int c0 = 8 * n + 2 * qc;
                const float b0 = bias[c0], b1 = bias[c0 + 1];
                *(float2*)(dst + c0) =
                    make_float2(to_tf32(C[n][0] + b0), to_tf32(C[n][1] + b1));
                *(float2*)(dst + 8 * DIM + c0) =
                    make_float2(to_tf32(C[n][2] + b0), to_tf32(C[n][3] + b1));
            }
        } else {
            const int bb = r0 >> 11;
            const int sr = r0 & 2047;
            float* base = g_vt + (size_t)bb * DIM * SEQ + sr;
            #pragma unroll
            for (int n = 0; n < 16; ++n) {
                const int d0 = 8 * n + 2 * qc;
                const float b0 = bias[d0], b1 = bias[d0 + 1];
                base[(size_t)d0 * SEQ]           = to_tf32(C[n][0] + b0);
                base[(size_t)(d0 + 1) * SEQ]     = to_tf32(C[n][1] + b1);
                base[(size_t)d0 * SEQ + 8]       = to_tf32(C[n][2] + b0);
                base[(size_t)(d0 + 1) * SEQ + 8] = to_tf32(C[n][3] + b1);
            }
        }
    }
}

// ===========================================================================
// Kernel 2: tensor-core flash attention.  BR=64, 128 threads (4 warps of 16
// query rows), grid (32, 8) = 256 CTAs, 2 CTAs per SM for barrier-decoupled
// latency hiding.  Single-buffered fragment-major swizzled K/V smem:
//   K frag: Kf[a:8][li:32][g:8] float4, swizzle (g ^ (li&7))
//   V frag: Vf[a:16][li:32][g:4] float4, swizzle (g ^ ((li>>1)&3))
// ===========================================================================
constexpr int KOFF  = 0;       // 8192 floats
constexpr int VOFF  = 8192;    // 8192 floats
constexpr int PSOFF = 16384;   // Ps[64][68]
constexpr int PSTRIDE = 68;
constexpr int SMEM_FLOATS = PSOFF + BR * PSTRIDE;   // 20736
constexpr int SMEM_BYTES  = SMEM_FLOATS * 4;        // 82944

__global__ __launch_bounds__(128, 2) void attn_kernel(
    const int* __restrict__ adj, float* __restrict__ out)
{
    extern __shared__ float sm[];
    float* const Ps = sm + PSOFF;

    const int t    = threadIdx.x;
    const int w    = t >> 5;
    const int lane = t & 31;
    const int qr   = lane >> 2;
    const int qc   = lane & 3;
    const int b    = blockIdx.y;
    const int row0 = blockIdx.x * BR;

    // ---- Q fragments in registers for the whole kernel ----
    float Qf[16][4];
    {
        const float* qb = g_q + (size_t)(b * SEQ + row0 + 16 * w) * DIM;
        #pragma unroll
        for (int kt = 0; kt < 16; ++kt) {
            const int c0 = 8 * kt + qc;
            Qf[kt][0] = qb[(size_t)qr * DIM + c0];
            Qf[kt][1] = qb[(size_t)(qr + 8) * DIM + c0];
            Qf[kt][2] = qb[(size_t)qr * DIM + c0 + 4];
            Qf[kt][3] = qb[(size_t)(qr + 8) * DIM + c0 + 4];
        }
    }

    float O[16][4];
    #pragma unroll
    for (int j = 0; j < 16; ++j)
        #pragma unroll
        for (int i = 0; i < 4; ++i) O[j][i] = 0.0f;

    float m0 = -INFINITY, m1 = -INFINITY, l0 = 0.0f, l1 = 0.0f;

    const int r0g = row0 + 16 * w + qr;
    const int r1g = r0g + 8;
    const int* adj0 = adj + ((size_t)b * SEQ + r0g) * SEQ;
    const int* adj1 = adj + ((size_t)b * SEQ + r1g) * SEQ;

    const float* kbase  = g_k  + (size_t)b * SEQ * DIM;
    const float* vtbase = g_vt + (size_t)b * DIM * SEQ;

    for (int c = 0; c < NCHUNK; ++c) {
        const int key0 = c * BC;

        // ---- fill K (fragment-major, swizzled) ----
        {
            const float4* kg = (const float4*)(kbase + (size_t)key0 * DIM);
            #pragma unroll
            for (int i = 0; i < 16; ++i) {
                const int f   = i * 128 + t;   // 0..2047
                const int key = f >> 5, c4 = f & 31;
                const float4 r = kg[f];
                float* blk = sm + KOFF + (key >> 3) * 1024;
                const int lib = (key & 7) * 4;
                const float* v = &r.x;
                #pragma unroll
                for (int e = 0; e < 4; ++e) {
                    const int li = lib + e;
                    blk[li * 32 + (((c4 >> 2) ^ (li & 7)) << 2) + (c4 & 3)] = v[e];
                }
            }
        }
        // ---- fill V (fragment-major, swizzled; from transposed gmem) ----
        {
            #pragma unroll
            for (int i = 0; i < 16; ++i) {
                const int f = i * 128 + t;     // 0..2047
                const int d = f >> 4, c4 = f & 15;
                const float4 r = *(const float4*)(vtbase + (size_t)d * SEQ + key0 + 4 * c4);
                float* blk = sm + VOFF + (d >> 3) * 512;
                const int lib = (d & 7) * 4;
                const float* v = &r.x;
                #pragma unroll
                for (int e = 0; e < 4; ++e) {
                    const int li = lib + e;
                    const int s  = (li >> 1) & 3;
                    blk[li * 16 + (((c4 >> 2) ^ s) << 2) + (c4 & 3)] = v[e];
                }
            }
        }
        __syncthreads();

        // ---- adjacency prefetch (hidden under QK mma) ----
        int2 A0[8], A1[8];
        #pragma unroll
        for (int jn = 0; jn < 8; ++jn) {
            const int col = key0 + 8 * jn + 2 * qc;
            A0[jn] = *(const int2*)(adj0 + col);
            A1[jn] = *(const int2*)(adj1 + col);
        }

        // ---- S = Q K^T ----
        float Sacc[8][4];
        #pragma unroll
        for (int j = 0; j < 8; ++j)
            #pragma unroll
            for (int i = 0; i < 4; ++i) Sacc[j][i] = 0.0f;

        #pragma unroll
        for (int a = 0; a < 8; ++a) {
            const float* kb = sm + KOFF + a * 1024 + lane * 32;
            #pragma unroll
            for (int g = 0; g < 8; ++g) {
                const float4 kf = *(const float4*)(kb + ((g ^ (lane & 7)) << 2));
                float bf0[2] = {kf.x, kf.y};
                float bf1[2] = {kf.z, kf.w};
                mma_tf32(Sacc[a], Qf[2 * g],     bf0);
                mma_tf32(Sacc[a], Qf[2 * g + 1], bf1);
            }
        }

        // ---- scale + adjacency bias ----
        float p[8][4];
        float mx0 = -INFINITY, mx1 = -INFINITY;
        #pragma unroll
        for (int jn = 0; jn < 8; ++jn) {
            p[jn][0] = fmaf(Sacc[jn][0], SCALE, A0[jn].x ? 0.0f : NEG_BIG);
            p[jn][1] = fmaf(Sacc[jn][1], SCALE, A0[jn].y ? 0.0f : NEG_BIG);
            p[jn][2] = fmaf(Sacc[jn][2], SCALE, A1[jn].x ? 0.0f : NEG_BIG);
            p[jn][3] = fmaf(Sacc[jn][3], SCALE, A1[jn].y ? 0.0f : NEG_BIG);
            mx0 = fmaxf(mx0, fmaxf(p[jn][0], p[jn][1]));
            mx1 = fmaxf(mx1, fmaxf(p[jn][2], p[jn][3]));
        }
        mx0 = fmaxf(mx0, __shfl_xor_sync(0xffffffffu, mx0, 1));
        mx0 = fmaxf(mx0, __shfl_xor_sync(0xffffffffu, mx0, 2));
        mx1 = fmaxf(mx1, __shfl_xor_sync(0xffffffffu, mx1, 1));
        mx1 = fmaxf(mx1, __shfl_xor_sync(0xffffffffu, mx1, 2));

        const float mn0 = fmaxf(m0, mx0);
        const float mn1 = fmaxf(m1, mx1);
        const float alpha0 = __expf(m0 - mn0);
        const float alpha1 = __expf(m1 - mn1);
        m0 = mn0; m1 = mn1;

        float sum0 = 0.0f, sum1 = 0.0f;
        #pragma unroll
        for (int jn = 0; jn < 8; ++jn) {
            p[jn][0] = __expf(p[jn][0] - mn0);
            p[jn][1] = __expf(p[jn][1] - mn0);
            p[jn][2] = __expf(p[jn][2] - mn1);
            p[jn][3] = __expf(p[jn][3] - mn1);
            sum0 += p[jn][0] + p[jn][1];
            sum1 += p[jn][2] + p[jn][3];
            float2* d0 = (float2*)(Ps + (16 * w + qr) * PSTRIDE + 8 * jn + 2 * qc);
            float2* d1 = (float2*)(Ps + (16 * w + qr + 8) * PSTRIDE + 8 * jn + 2 * qc);
            *d0 = make_float2(to_tf32(p[jn][0]), to_tf32(p[jn][1]));
            *d1 = make_float2(to_tf32(p[jn][2]), to_tf32(p[jn][3]));
        }
        sum0 += __shfl_xor_sync(0xffffffffu, sum0, 1);
        sum0 += __shfl_xor_sync(0xffffffffu, sum0, 2);
        sum1 += __shfl_xor_sync(0xffffffffu, sum1, 1);
        sum1 += __shfl_xor_sync(0xffffffffu, sum1, 2);
        l0 = l0 * alpha0 + sum0;
        l1 = l1 * alpha1 + sum1;

        #pragma unroll
        for (int jn = 0; jn < 16; ++jn) {
            O[jn][0] *= alpha0; O[jn][1] *= alpha0;
            O[jn][2] *= alpha1; O[jn][3] *= alpha1;
        }

        __syncwarp();   // P visible to quad-mates

        // ---- O += P V ----
        #pragma unroll
        for (int g = 0; g < 4; ++g) {
            float a0[4], a1[4];
            const float* pp0 = Ps + (16 * w + qr) * PSTRIDE + 16 * g + qc;
            a0[0] = pp0[0];
            a0[1] = pp0[8 * PSTRIDE];
            a0[2] = pp0[4];
            a0[3] = pp0[8 * PSTRIDE + 4];
            a1[0] = pp0[8];
            a1[1] = pp0[8 * PSTRIDE + 8];
            a1[2] = pp0[12];
            a1[3] = pp0[8 * PSTRIDE + 12];
            const int sw = ((lane >> 1) & 3);
            #pragma unroll
            for (int a = 0; a < 16; ++a) {
                const float* vb = sm + VOFF + a * 512 + lane * 16;
                const float4 vf = *(const float4*)(vb + ((g ^ sw) << 2));
                float bf0[2] = {vf.x, vf.y};
                float bf1[2] = {vf.z, vf.w};
                mma_tf32(O[a], a0, bf0);
                mma_tf32(O[a], a1, bf1);
            }
        }

        __syncthreads();   // all K/V/Ps reads done before next chunk's fill
    }

    // ---- epilogue: normalize, ELU, store ----
    {
        const float li0 = 1.0f / l0;
        const float li1 = 1.0f / l1;
        float* out0 = out + ((size_t)b * SEQ + r0g) * DIM;
        float* out1 = out + ((size_t)b * SEQ + r1g) * DIM;
        #pragma unroll
        for (int jn = 0; jn < 16; ++jn) {
            const int col = 8 * jn + 2 * qc;
            *(float2*)(out0 + col) =
                make_float2(elu1(O[jn][0] * li0), elu1(O[jn][1] * li0));
            *(float2*)(out1 + col) =
                make_float2(elu1(O[jn][2] * li1), elu1(O[jn][3] * li1));
        }
    }
}

// ---------------------------------------------------------------------------
extern "C" void kernel_launch(void* const* d_in, const int* in_sizes, int n_in,
                              void* d_out, int out_size)
{
    const float* x   = (const float*)d_in[0];
    const int*   adj = (const int*)  d_in[1];
    const float* Wq  = (const float*)d_in[2];
    const float* bq  = (const float*)d_in[3];
    const float* Wk  = (const float*)d_in[4];
    const float* bk  = (const float*)d_in[5];
    const float* Wv  = (const float*)d_in[6];
    const float* bv  = (const float*)d_in[7];
    float* out = (float*)d_out;

    cudaFuncSetAttribute(proj_kernel,
                         cudaFuncAttributeMaxDynamicSharedMemorySize, PSM_BYTES);
    cudaFuncSetAttribute(attn_kernel,
                         cudaFuncAttributeMaxDynamicSharedMemorySize, SMEM_BYTES);

    proj_kernel<<<(BATCH * SEQ) / 128, 256, PSM_BYTES>>>(
        x, Wq, bq, Wk, bk, Wv, bv);

    attn_kernel<<<dim3(SEQ / BR, BATCH), 128, SMEM_BYTES>>>(adj, out);
}

// round 8
// speedup vs baseline: 2.5188x; 1.1341x over previous
#include <cuda_runtime.h>
#include <math.h>

// Problem constants
constexpr int BATCH = 8;
constexpr int SEQ   = 2048;
constexpr int DIM   = 128;
constexpr int BR    = 64;    // query rows per CTA (2 CTAs / SM)
constexpr int BC    = 64;    // keys per chunk
constexpr int NCHUNK = SEQ / BC;
constexpr float NEG_BIG = -10000.0f;
constexpr float SCALE   = 0.0883883476483184405f; // 1/sqrt(128)

// Scratch: row-major projections (tf32-rounded) + fragment-major K/V blobs.
__device__ float g_q [BATCH * SEQ * DIM];
__device__ float g_k [BATCH * SEQ * DIM];
__device__ float g_v [BATCH * SEQ * DIM];
__device__ float g_kf[BATCH * NCHUNK * 8192];   // K fragment blobs, 32KB each
__device__ float g_vf[BATCH * NCHUNK * 8192];   // V fragment blobs, 32KB each

__device__ __forceinline__ float to_tf32(float x) {
    unsigned u;
    asm("cvt.rna.tf32.f32 %0, %1;" : "=r"(u) : "f"(x));
    return __uint_as_float(u);
}

// m16n8k8 tf32 tensor-core mma (fp32 accumulate)
__device__ __forceinline__ void mma_tf32(float (&c)[4], const float (&a)[4],
                                         const float (&bf)[2])
{
    const unsigned* A = reinterpret_cast<const unsigned*>(a);
    const unsigned* B = reinterpret_cast<const unsigned*>(bf);
    asm volatile(
        "mma.sync.aligned.m16n8k8.row.col.f32.tf32.tf32.f32 "
        "{%0,%1,%2,%3}, {%4,%5,%6,%7}, {%8,%9}, {%0,%1,%2,%3};\n"
        : "+f"(c[0]), "+f"(c[1]), "+f"(c[2]), "+f"(c[3])
        : "r"(A[0]), "r"(A[1]), "r"(A[2]), "r"(A[3]), "r"(B[0]), "r"(B[1]));
}

__device__ __forceinline__ void cp16(void* smem, const void* g) {
    unsigned s = (unsigned)__cvta_generic_to_shared(smem);
    asm volatile("cp.async.ca.shared.global [%0], [%1], 16;\n"
                 :: "r"(s), "l"(g));
}
__device__ __forceinline__ void cp_commit_wait0() {
    asm volatile("cp.async.commit_group;\n");
    asm volatile("cp.async.wait_group 0;\n");
}

__device__ __forceinline__ float elu1(float x) {
    return x > 0.0f ? x : expm1f(x);
}

// ===========================================================================
// Kernel 1: QKV projection, tf32 tensor cores with hi/lo split (fp32-quality).
// Grid = 128 CTAs (128-row tile each), 256 threads. All outputs row-major.
// ===========================================================================
constexpr int PSM_FLOATS = 2 * 128 * 132;
constexpr int PSM_BYTES  = PSM_FLOATS * 4;

__global__ __launch_bounds__(256) void proj_kernel(
    const float* __restrict__ x,
    const float* __restrict__ Wq, const float* __restrict__ bq,
    const float* __restrict__ Wk, const float* __restrict__ bk,
    const float* __restrict__ Wv, const float* __restrict__ bv)
{
    extern __shared__ float psm[];
    float* const Xs = psm;
    float* const Ws = psm + 128 * 132;

    const int t    = threadIdx.x;
    const int w    = t >> 5;
    const int lane = t & 31;
    const int qr   = lane >> 2;
    const int qc   = lane & 3;
    const int row0 = blockIdx.x * 128;

    {
        const float4* xg = (const float4*)(x + (size_t)row0 * DIM);
        #pragma unroll
        for (int i = 0; i < 16; ++i) {
            const int f = i * 256 + t;
            const int r = f >> 5, c4 = f & 31;
            *(float4*)(Xs + r * 132 + 4 * c4) = xg[f];
        }
    }

    #pragma unroll 1
    for (int gy = 0; gy < 3; ++gy) {
        const float* W    = gy == 0 ? Wq : (gy == 1 ? Wk : Wv);
        const float* bias = gy == 0 ? bq : (gy == 1 ? bk : bv);

        __syncthreads();
        {
            const float4* wg = (const float4*)W;
            #pragma unroll
            for (int i = 0; i < 16; ++i) {
                const int f = i * 256 + t;
                const int r = f >> 5, c4 = f & 31;
                *(float4*)(Ws + r * 132 + 4 * c4) = wg[f];
            }
        }
        __syncthreads();

        float C[16][4];
        #pragma unroll
        for (int n = 0; n < 16; ++n)
            #pragma unroll
            for (int i = 0; i < 4; ++i) C[n][i] = 0.0f;

        #pragma unroll
        for (int kt = 0; kt < 16; ++kt) {
            float ah[4], al[4];
            {
                const float* ap = Xs + (16 * w + qr) * 132 + 8 * kt + qc;
                float a0 = ap[0], a1 = ap[8 * 132], a2 = ap[4], a3 = ap[8 * 132 + 4];
                ah[0] = to_tf32(a0); al[0] = to_tf32(a0 - ah[0]);
                ah[1] = to_tf32(a1); al[1] = to_tf32(a1 - ah[1]);
                ah[2] = to_tf32(a2); al[2] = to_tf32(a2 - ah[2]);
                ah[3] = to_tf32(a3); al[3] = to_tf32(a3 - ah[3]);
            }
            #pragma unroll
            for (int n = 0; n < 16; ++n) {
                const float* bp = Ws + (8 * kt + qc) * 132 + 8 * n + qr;
                const float b0 = bp[0], b1 = bp[4 * 132];
                float bh[2], bl[2];
                bh[0] = to_tf32(b0); bl[0] = to_tf32(b0 - bh[0]);
                bh[1] = to_tf32(b1); bl[1] = to_tf32(b1 - bh[1]);
                mma_tf32(C[n], ah, bh);
                mma_tf32(C[n], al, bh);
                mma_tf32(C[n], ah, bl);
            }
        }

        const int r0 = row0 + 16 * w + qr;
        float* dst = (gy == 0 ? g_q : (gy == 1 ? g_k : g_v)) + (size_t)r0 * DIM;
        #pragma unroll
        for (int n = 0; n < 16; ++n) {
            const int c0 = 8 * n + 2 * qc;
            const float b0 = bias[c0], b1 = bias[c0 + 1];
            *(float2*)(dst + c0) =
                make_float2(to_tf32(C[n][0] + b0), to_tf32(C[n][1] + b1));
            *(float2*)(dst + 8 * DIM + c0) =
                make_float2(to_tf32(C[n][2] + b0), to_tf32(C[n][3] + b1));
        }
    }
}

// ===========================================================================
// Kernel 1.5: repack K and V into fragment-major 32KB blobs per (b, chunk).
// The blob image is exactly what the attention kernel consumes via cp.async.
// K frag: [a:8][li:32][pos:8] float4, pos = (d>>4) ^ (li&7), li = 4*(key&7)+(d&3)
// V frag: [a:16][li:32][pos:4] float4, pos = (key>>4) ^ ((li>>1)&3),
//         li = 4*(d&7)+(key&3)
// Grid (NCHUNK, BATCH), 128 threads.
// ===========================================================================
__global__ __launch_bounds__(128) void repack_kernel()
{
    __shared__ float buf[8192];
    const int t  = threadIdx.x;
    const int c  = blockIdx.x;
    const int b  = blockIdx.y;
    const int key0 = c * BC;

    // ---- K blob ----
    {
        const float4* kg = (const float4*)(g_k + (size_t)(b * SEQ + key0) * DIM);
        #pragma unroll
        for (int i = 0; i < 16; ++i) {
            const int f   = i * 128 + t;     // 0..2047
            const int key = f >> 5, c4 = f & 31;
            const float4 r = kg[f];
            float* blk = buf + (key >> 3) * 1024;
            const int lib = (key & 7) * 4;
            const float* v = &r.x;
            #pragma unroll
            for (int e = 0; e < 4; ++e) {
                const int li = lib + e;
                blk[li * 32 + (((c4 >> 2) ^ (li & 7)) << 2) + (c4 & 3)] = v[e];
            }
        }
    }
    __syncthreads();
    {
        float4* dst = (float4*)g_kf + (size_t)(b * NCHUNK + c) * 2048;
        const float4* src = (const float4*)buf;
        #pragma unroll
        for (int i = 0; i < 16; ++i) dst[i * 128 + t] = src[i * 128 + t];
    }
    __syncthreads();

    // ---- V blob (transpose happens here, from row-major g_v) ----
    {
        const float4* vg = (const float4*)(g_v + (size_t)(b * SEQ + key0) * DIM);
        #pragma unroll
        for (int i = 0; i < 16; ++i) {
            const int f   = i * 128 + t;     // 0..2047
            const int key = f >> 5, c4 = f & 31;   // d = 4*c4+e
            const float4 r = vg[f];
            const float* v = &r.x;
            #pragma unroll
            for (int e = 0; e < 4; ++e) {
                const int d  = 4 * c4 + e;
                const int li = 4 * (d & 7) + (key & 3);
                const int pos = (key >> 4) ^ ((li >> 1) & 3);
                buf[(d >> 3) * 512 + li * 16 + pos * 4 + ((key >> 2) & 3)] = v[e];
            }
        }
    }
    __syncthreads();
    {
        float4* dst = (float4*)g_vf + (size_t)(b * NCHUNK + c) * 2048;
        const float4* src = (const float4*)buf;
        #pragma unroll
        for (int i = 0; i < 16; ++i) dst[i * 128 + t] = src[i * 128 + t];
    }
}

// ===========================================================================
// Kernel 2: tensor-core flash attention.  BR=64, 128 threads, grid (32,8),
// 2 CTAs/SM.  K/V tiles arrive pre-packed via cp.async straight copy.
// ===========================================================================
constexpr int KOFF  = 0;       // 8192 floats
constexpr int VOFF  = 8192;    // 8192 floats
constexpr int PSOFF = 16384;   // Ps[64][68]
constexpr int PSTRIDE = 68;
constexpr int SMEM_FLOATS = PSOFF + BR * PSTRIDE;   // 20736
constexpr int SMEM_BYTES  = SMEM_FLOATS * 4;        // 82944

__global__ __launch_bounds__(128, 2) void attn_kernel(
    const int* __restrict__ adj, float* __restrict__ out)
{
    extern __shared__ float sm[];
    float* const Ps = sm + PSOFF;

    const int t    = threadIdx.x;
    const int w    = t >> 5;
    const int lane = t & 31;
    const int qr   = lane >> 2;
    const int qc   = lane & 3;
    const int b    = blockIdx.y;
    const int row0 = blockIdx.x * BR;

    // ---- Q fragments in registers for the whole kernel ----
    float Qf[16][4];
    {
        const float* qb = g_q + (size_t)(b * SEQ + row0 + 16 * w) * DIM;
        #pragma unroll
        for (int kt = 0; kt < 16; ++kt) {
            const int c0 = 8 * kt + qc;
            Qf[kt][0] = qb[(size_t)qr * DIM + c0];
            Qf[kt][1] = qb[(size_t)(qr + 8) * DIM + c0];
            Qf[kt][2] = qb[(size_t)qr * DIM + c0 + 4];
            Qf[kt][3] = qb[(size_t)(qr + 8) * DIM + c0 + 4];
        }
    }

    float O[16][4];
    #pragma unroll
    for (int j = 0; j < 16; ++j)
        #pragma unroll
        for (int i = 0; i < 4; ++i) O[j][i] = 0.0f;

    float m0 = -INFINITY, m1 = -INFINITY, l0 = 0.0f, l1 = 0.0f;

    const int r0g = row0 + 16 * w + qr;
    const int r1g = r0g + 8;
    const int* adj0 = adj + ((size_t)b * SEQ + r0g) * SEQ;
    const int* adj1 = adj + ((size_t)b * SEQ + r1g) * SEQ;

    for (int c = 0; c < NCHUNK; ++c) {
        const int key0 = c * BC;

        // ---- straight cp.async copy of the pre-packed blobs ----
        {
            const float4* ks = (const float4*)g_kf + (size_t)(b * NCHUNK + c) * 2048;
            const float4* vs = (const float4*)g_vf + (size_t)(b * NCHUNK + c) * 2048;
            float4* kd = (float4*)(sm + KOFF);
            float4* vd = (float4*)(sm + VOFF);
            #pragma unroll
            for (int i = 0; i < 16; ++i) cp16(kd + i * 128 + t, ks + i * 128 + t);
            #pragma unroll
            for (int i = 0; i < 16; ++i) cp16(vd + i * 128 + t, vs + i * 128 + t);
            cp_commit_wait0();
        }
        __syncthreads();

        // ---- adjacency prefetch (hidden under QK mma) ----
        int2 A0[8], A1[8];
        #pragma unroll
        for (int jn = 0; jn < 8; ++jn) {
            const int col = key0 + 8 * jn + 2 * qc;
            A0[jn] = *(const int2*)(adj0 + col);
            A1[jn] = *(const int2*)(adj1 + col);
        }

        // ---- S = Q K^T (g outer: 8 independent accumulator chains) ----
        float Sacc[8][4];
        #pragma unroll
        for (int j = 0; j < 8; ++j)
            #pragma unroll
            for (int i = 0; i < 4; ++i) Sacc[j][i] = 0.0f;

        #pragma unroll
        for (int g = 0; g < 8; ++g) {
            const int off = (g ^ (lane & 7)) << 2;
            #pragma unroll
            for (int a = 0; a < 8; ++a) {
                const float4 kf = *(const float4*)(sm + KOFF + a * 1024 + lane * 32 + off);
                float bf0[2] = {kf.x, kf.y};
                float bf1[2] = {kf.z, kf.w};
                mma_tf32(Sacc[a], Qf[2 * g],     bf0);
                mma_tf32(Sacc[a], Qf[2 * g + 1], bf1);
            }
        }

        // ---- scale + adjacency bias (in place) ----
        float mx0 = -INFINITY, mx1 = -INFINITY;
        #pragma unroll
        for (int jn = 0; jn < 8; ++jn) {
            Sacc[jn][0] = fmaf(Sacc[jn][0], SCALE, A0[jn].x ? 0.0f : NEG_BIG);
            Sacc[jn][1] = fmaf(Sacc[jn][1], SCALE, A0[jn].y ? 0.0f : NEG_BIG);
            Sacc[jn][2] = fmaf(Sacc[jn][2], SCALE, A1[jn].x ? 0.0f : NEG_BIG);
            Sacc[jn][3] = fmaf(Sacc[jn][3], SCALE, A1[jn].y ? 0.0f : NEG_BIG);
            mx0 = fmaxf(mx0, fmaxf(Sacc[jn][0], Sacc[jn][1]));
            mx1 = fmaxf(mx1, fmaxf(Sacc[jn][2], Sacc[jn][3]));
        }
        mx0 = fmaxf(mx0, __shfl_xor_sync(0xffffffffu, mx0, 1));
        mx0 = fmaxf(mx0, __shfl_xor_sync(0xffffffffu, mx0, 2));
        mx1 = fmaxf(mx1, __shfl_xor_sync(0xffffffffu, mx1, 1));
        mx1 = fmaxf(mx1, __shfl_xor_sync(0xffffffffu, mx1, 2));

        const float mn0 = fmaxf(m0, mx0);
        const float mn1 = fmaxf(m1, mx1);
        const float alpha0 = __expf(m0 - mn0);
        const float alpha1 = __expf(m1 - mn1);
        m0 = mn0; m1 = mn1;

        float sum0 = 0.0f, sum1 = 0.0f;
        #pragma unroll
        for (int jn = 0; jn < 8; ++jn) {
            Sacc[jn][0] = __expf(Sacc[jn][0] - mn0);
            Sacc[jn][1] = __expf(Sacc[jn][1] - mn0);
            Sacc[jn][2] = __expf(Sacc[jn][2] - mn1);
            Sacc[jn][3] = __expf(Sacc[jn][3] - mn1);
            sum0 += Sacc[jn][0] + Sacc[jn][1];
            sum1 += Sacc[jn][2] + Sacc[jn][3];
            float2* d0 = (float2*)(Ps + (16 * w + qr) * PSTRIDE + 8 * jn + 2 * qc);
            float2* d1 = (float2*)(Ps + (16 * w + qr + 8) * PSTRIDE + 8 * jn + 2 * qc);
            *d0 = make_float2(to_tf32(Sacc[jn][0]), to_tf32(Sacc[jn][1]));
            *d1 = make_float2(to_tf32(Sacc[jn][2]), to_tf32(Sacc[jn][3]));
        }
        sum0 += __shfl_xor_sync(0xffffffffu, sum0, 1);
        sum0 += __shfl_xor_sync(0xffffffffu, sum0, 2);
        sum1 += __shfl_xor_sync(0xffffffffu, sum1, 1);
        sum1 += __shfl_xor_sync(0xffffffffu, sum1, 2);
        l0 = l0 * alpha0 + sum0;
        l1 = l1 * alpha1 + sum1;

        #pragma unroll
        for (int jn = 0; jn < 16; ++jn) {
            O[jn][0] *= alpha0; O[jn][1] *= alpha0;
            O[jn][2] *= alpha1; O[jn][3] *= alpha1;
        }

        __syncwarp();   // P visible to quad-mates

        // ---- O += P V ----
        #pragma unroll
        for (int g = 0; g < 4; ++g) {
            float a0[4], a1[4];
            const float* pp0 = Ps + (16 * w + qr) * PSTRIDE + 16 * g + qc;
            a0[0] = pp0[0];
            a0[1] = pp0[8 * PSTRIDE];
            a0[2] = pp0[4];
            a0[3] = pp0[8 * PSTRIDE + 4];
            a1[0] = pp0[8];
            a1[1] = pp0[8 * PSTRIDE + 8];
            a1[2] = pp0[12];
            a1[3] = pp0[8 * PSTRIDE + 12];
            const int sw = ((lane >> 1) & 3);
            #pragma unroll
            for (int a = 0; a < 16; ++a) {
                const float* vb = sm + VOFF + a * 512 + lane * 16;
                const float4 vf = *(const float4*)(vb + ((g ^ sw) << 2));
                float bf0[2] = {vf.x, vf.y};
                float bf1[2] = {vf.z, vf.w};
                mma_tf32(O[a], a0, bf0);
                mma_tf32(O[a], a1, bf1);
            }
        }

        __syncthreads();   // all K/V/Ps reads done before next chunk's copy
    }

    // ---- epilogue: normalize, ELU, store ----
    {
        const float li0 = 1.0f / l0;
        const float li1 = 1.0f / l1;
        float* out0 = out + ((size_t)b * SEQ + r0g) * DIM;
        float* out1 = out + ((size_t)b * SEQ + r1g) * DIM;
        #pragma unroll
        for (int jn = 0; jn < 16; ++jn) {
            const int col = 8 * jn + 2 * qc;
            *(float2*)(out0 + col) =
                make_float2(elu1(O[jn][0] * li0), elu1(O[jn][1] * li0));
            *(float2*)(out1 + col) =
                make_float2(elu1(O[jn][2] * li1), elu1(O[jn][3] * li1));
        }
    }
}

// ---------------------------------------------------------------------------
extern "C" void kernel_launch(void* const* d_in, const int* in_sizes, int n_in,
                              void* d_out, int out_size)
{
    const float* x   = (const float*)d_in[0];
    const int*   adj = (const int*)  d_in[1];
    const float* Wq  = (const float*)d_in[2];
    const float* bq  = (const float*)d_in[3];
    const float* Wk  = (const float*)d_in[4];
    const float* bk  = (const float*)d_in[5];
    const float* Wv  = (const float*)d_in[6];
    const float* bv  = (const float*)d_in[7];
    float* out = (float*)d_out;

    cudaFuncSetAttribute(proj_kernel,
                         cudaFuncAttributeMaxDynamicSharedMemorySize, PSM_BYTES);
    cudaFuncSetAttribute(attn_kernel,
                         cudaFuncAttributeMaxDynamicSharedMemorySize, SMEM_BYTES);

    proj_kernel<<<(BATCH * SEQ) / 128, 256, PSM_BYTES>>>(
        x, Wq, bq, Wk, bk, Wv, bv);

    repack_kernel<<<dim3(NCHUNK, BATCH), 128>>>();

    attn_kernel<<<dim3(SEQ / BR, BATCH), 128, SMEM_BYTES>>>(adj, out);
}

// round 10
// speedup vs baseline: 2.9392x; 1.1669x over previous
#include <cuda_runtime.h>
#include <math.h>

// Problem constants
constexpr int BATCH = 8;
constexpr int SEQ   = 2048;
constexpr int DIM   = 128;
constexpr int BR    = 64;    // query rows per CTA (2 CTAs / SM)
constexpr int BC    = 64;    // keys per chunk
constexpr int NCHUNK = SEQ / BC;
constexpr float NEG_BIG = -10000.0f;
constexpr float SCALE   = 0.0883883476483184405f; // 1/sqrt(128)

// Scratch: Q row-major (tf32-rounded) + fragment-major K/V blobs (written
// directly by proj's epilogue; 32KB per (batch, chunk)).
__device__ float g_q [BATCH * SEQ * DIM];
__device__ float g_kf[BATCH * NCHUNK * 8192];
__device__ float g_vf[BATCH * NCHUNK * 8192];

__device__ __forceinline__ float to_tf32(float x) {
    unsigned u;
    asm("cvt.rna.tf32.f32 %0, %1;" : "=r"(u) : "f"(x));
    return __uint_as_float(u);
}

// m16n8k8 tf32 tensor-core mma (fp32 accumulate)
__device__ __forceinline__ void mma_tf32(float (&c)[4], const float (&a)[4],
                                         const float (&bf)[2])
{
    const unsigned* A = reinterpret_cast<const unsigned*>(a);
    const unsigned* B = reinterpret_cast<const unsigned*>(bf);
    asm volatile(
        "mma.sync.aligned.m16n8k8.row.col.f32.tf32.tf32.f32 "
        "{%0,%1,%2,%3}, {%4,%5,%6,%7}, {%8,%9}, {%0,%1,%2,%3};\n"
        : "+f"(c[0]), "+f"(c[1]), "+f"(c[2]), "+f"(c[3])
        : "r"(A[0]), "r"(A[1]), "r"(A[2]), "r"(A[3]), "r"(B[0]), "r"(B[1]));
}

__device__ __forceinline__ void cp16(void* smem, const void* g) {
    unsigned s = (unsigned)__cvta_generic_to_shared(smem);
    asm volatile("cp.async.cg.shared.global [%0], [%1], 16;\n"
                 :: "r"(s), "l"(g));
}
__device__ __forceinline__ void cp_commit_wait0() {
    asm volatile("cp.async.commit_group;\n");
    asm volatile("cp.async.wait_group 0;\n");
}

__device__ __forceinline__ float elu1(float x) {
    return x > 0.0f ? x : expm1f(x);
}

// ===========================================================================
// Kernel 1: fused QKV projection + K/V blob packing.
// Grid = 128 CTAs (one 128-row tile = one batch-slice of 2 chunks), 256 thr.
// W is hi/lo-split ONCE at load time into interleaved (h,l) pairs:
//   Whl[row*264 + 2*col] = tf32_hi,  [.. + 1] = tf32_lo
// Inner loop: 2 x LDS.64 + 3 mma per fragment, no conversions.
// Epilogue: Q stored row-major; K/V scattered into fragment-major blob image
// in smem (reusing Whl) and copied out as one contiguous 64KB block.
// ===========================================================================
constexpr int WSTRIDE    = 264;                        // 128 (h,l) pairs + pad
constexpr int PSM_FLOATS = 128 * 132 + 128 * WSTRIDE;  // Xs + Whl = 50688
constexpr int PSM_BYTES  = PSM_FLOATS * 4;             // 202752

__global__ __launch_bounds__(256) void proj_kernel(
    const float* __restrict__ x,
    const float* __restrict__ Wq, const float* __restrict__ bq,
    const float* __restrict__ Wk, const float* __restrict__ bk,
    const float* __restrict__ Wv, const float* __restrict__ bv)
{
    extern __shared__ float psm[];
    float* const Xs  = psm;
    float* const Whl = psm + 128 * 132;

    const int t    = threadIdx.x;
    const int w    = t >> 5;
    const int lane = t & 31;
    const int qr   = lane >> 2;
    const int qc   = lane & 3;
    const int row0 = blockIdx.x * 128;
    const int bb    = row0 >> 11;           // batch
    const int cbase = (row0 & 2047) >> 6;   // first chunk of this tile

    // load X tile once
    {
        const float4* xg = (const float4*)(x + (size_t)row0 * DIM);
        #pragma unroll
        for (int i = 0; i < 16; ++i) {
            const int f = i * 256 + t;
            const int r = f >> 5, c4 = f & 31;
            *(float4*)(Xs + r * 132 + 4 * c4) = xg[f];
        }
    }

    #pragma unroll 1
    for (int gy = 0; gy < 3; ++gy) {
        const float* W    = gy == 0 ? Wq : (gy == 1 ? Wk : Wv);
        const float* bias = gy == 0 ? bq : (gy == 1 ? bk : bv);

        __syncthreads();   // previous Whl readers (mma or blob copy) done
        {
            const float4* wg = (const float4*)W;
            #pragma unroll
            for (int i = 0; i < 16; ++i) {
                const int f = i * 256 + t;
                const int r = f >> 5, c4 = f & 31;
                const float4 v = wg[f];
                float hx = to_tf32(v.x), hy = to_tf32(v.y);
                float hz = to_tf32(v.z), hw = to_tf32(v.w);
                float* base = Whl + r * WSTRIDE + 8 * c4;
                ((float4*)base)[0] =
                    make_float4(hx, to_tf32(v.x - hx), hy, to_tf32(v.y - hy));
                ((float4*)base)[1] =
                    make_float4(hz, to_tf32(v.z - hz), hw, to_tf32(v.w - hw));
            }
        }
        __syncthreads();

        float C[16][4];
        #pragma unroll
        for (int n = 0; n < 16; ++n)
            #pragma unroll
            for (int i = 0; i < 4; ++i) C[n][i] = 0.0f;

        #pragma unroll
        for (int kt = 0; kt < 16; ++kt) {
            float ah[4], al[4];
            {
                const float* ap = Xs + (16 * w + qr) * 132 + 8 * kt + qc;
                float a0 = ap[0], a1 = ap[8 * 132], a2 = ap[4], a3 = ap[8 * 132 + 4];
                ah[0] = to_tf32(a0); al[0] = to_tf32(a0 - ah[0]);
                ah[1] = to_tf32(a1); al[1] = to_tf32(a1 - ah[1]);
                ah[2] = to_tf32(a2); al[2] = to_tf32(a2 - ah[2]);
                ah[3] = to_tf32(a3); al[3] = to_tf32(a3 - ah[3]);
            }
            const float* brow = Whl + (8 * kt + qc) * WSTRIDE + 2 * qr;
            #pragma unroll
            for (int n = 0; n < 16; ++n) {
                const float2 p0 = *(const float2*)(brow + 16 * n);
                const float2 p1 = *(const float2*)(brow + 16 * n + 4 * WSTRIDE);
                float bh[2] = {p0.x, p1.x};
                float bl[2] = {p0.y, p1.y};
                mma_tf32(C[n], ah, bh);
                mma_tf32(C[n], al, bh);
                mma_tf32(C[n], ah, bl);
            }
        }

        const int rA = 16 * w + qr;        // tile-local row (0..127)
        if (gy == 0) {
            // Q: row-major, tf32-rounded
            float* dst = g_q + (size_t)(row0 + rA) * DIM;
            #pragma unroll
            for (int n = 0; n < 16; ++n) {
                const int c0 = 8 * n + 2 * qc;
                const float b0 = bias[c0], b1 = bias[c0 + 1];
                *(float2*)(dst + c0) =
                    make_float2(to_tf32(C[n][0] + b0), to_tf32(C[n][1] + b1));
                *(float2*)(dst + 8 * DIM + c0) =
                    make_float2(to_tf32(C[n][2] + b0), to_tf32(C[n][3] + b1));
            }
        } else {
            // K or V: scatter into fragment-major blob image (reuse Whl)
            __syncthreads();   // all Whl mma reads complete
            float* const stage = Whl;      // 16384 floats used
            #pragma unroll
            for (int n = 0; n < 16; ++n) {
                const int d0 = 8 * n + 2 * qc;
                const float b0 = bias[d0], b1 = bias[d0 + 1];
                float vv[4] = { to_tf32(C[n][0] + b0), to_tf32(C[n][1] + b1),
                                to_tf32(C[n][2] + b0), to_tf32(C[n][3] + b1) };
                #pragma unroll
                for (int e = 0; e < 4; ++e) {
                    const int kk = rA + ((e >> 1) << 3);   // +8 for e=2,3
                    const int d  = d0 + (e & 1);
                    const int cs = kk >> 6;
                    const int kc = kk & 63;
                    int addr;
                    if (gy == 1) {
                        const int li = 4 * (kc & 7) + (d & 3);
                        addr = cs * 8192 + (kc >> 3) * 1024 + li * 32 +
                               (((d >> 4) ^ (li & 7)) << 2) + ((d >> 2) & 3);
                    } else {
                        const int li = 4 * (d & 7) + (kc & 3);
                        addr = cs * 8192 + (d >> 3) * 512 + li * 16 +
                               ((((kc >> 4) & 3) ^ ((li >> 1) & 3)) << 2) +
                               ((kc >> 2) & 3);
                    }
                    stage[addr] = vv[e];
                }
            }
            __syncthreads();   // blob image complete
            float4* dst = (float4*)(gy == 1 ? g_kf : g_vf) +
                          (size_t)(bb * NCHUNK + cbase) * 2048;
            const float4* src = (const float4*)stage;
            #pragma unroll
            for (int i = 0; i < 16; ++i)
                dst[i * 256 + t] = src[i * 256 + t];
        }
    }
}

// ===========================================================================
// Kernel 2: tensor-core flash attention.  BR=64, 128 threads, grid (32,8),
// 2 CTAs/SM.  K/V tiles arrive pre-packed via cp.async.cg straight copy.
// ===========================================================================
constexpr int KOFF  = 0;       // 8192 floats
constexpr int VOFF  = 8192;    // 8192 floats
constexpr int PSOFF = 16384;   // Ps[64][68]
constexpr int PSTRIDE = 68;
constexpr int SMEM_FLOATS = PSOFF + BR * PSTRIDE;   // 20736
constexpr int SMEM_BYTES  = SMEM_FLOATS * 4;        // 82944

__global__ __launch_bounds__(128, 2) void attn_kernel(
    const int* __restrict__ adj, float* __restrict__ out)
{
    extern __shared__ float sm[];
    float* const Ps = sm + PSOFF;

    const int t    = threadIdx.x;
    const int w    = t >> 5;
    const int lane = t & 31;
    const int qr   = lane >> 2;
    const int qc   = lane & 3;
    const int b    = blockIdx.y;
    const int row0 = blockIdx.x * BR;

    // ---- Q fragments in registers for the whole kernel ----
    float Qf[16][4];
    {
        const float* qb = g_q + (size_t)(b * SEQ + row0 + 16 * w) * DIM;
        #pragma unroll
        for (int kt = 0; kt < 16; ++kt) {
            const int c0 = 8 * kt + qc;
            Qf[kt][0] = qb[(size_t)qr * DIM + c0];
            Qf[kt][1] = qb[(size_t)(qr + 8) * DIM + c0];
            Qf[kt][2] = qb[(size_t)qr * DIM + c0 + 4];
            Qf[kt][3] = qb[(size_t)(qr + 8) * DIM + c0 + 4];
        }
    }

    float O[16][4];
    #pragma unroll
    for (int j = 0; j < 16; ++j)
        #pragma unroll
        for (int i = 0; i < 4; ++i) O[j][i] = 0.0f;

    float m0 = -INFINITY, m1 = -INFINITY, l0 = 0.0f, l1 = 0.0f;

    const int r0g = row0 + 16 * w + qr;
    const int r1g = r0g + 8;
    const int* adj0 = adj + ((size_t)b * SEQ + r0g) * SEQ;
    const int* adj1 = adj + ((size_t)b * SEQ + r1g) * SEQ;

    for (int c = 0; c < NCHUNK; ++c) {
        const int key0 = c * BC;

        // ---- straight cp.async.cg copy of the pre-packed blobs ----
        {
            const float4* ks = (const float4*)g_kf + (size_t)(b * NCHUNK + c) * 2048;
            const float4* vs = (const float4*)g_vf + (size_t)(b * NCHUNK + c) * 2048;
            float4* kd = (float4*)(sm + KOFF);
            float4* vd = (float4*)(sm + VOFF);
            #pragma unroll
            for (int i = 0; i < 16; ++i) cp16(kd + i * 128 + t, ks + i * 128 + t);
            #pragma unroll
            for (int i = 0; i < 16; ++i) cp16(vd + i * 128 + t, vs + i * 128 + t);
            cp_commit_wait0();
        }
        __syncthreads();

        // ---- adjacency prefetch, streaming (evict-first; hidden under mma) ----
        int2 A0[8], A1[8];
        #pragma unroll
        for (int jn = 0; jn < 8; ++jn) {
            const int col = key0 + 8 * jn + 2 * qc;
            A0[jn] = __ldcs((const int2*)(adj0 + col));
            A1[jn] = __ldcs((const int2*)(adj1 + col));
        }

        // ---- S = Q K^T (g outer: 8 independent accumulator chains) ----
        float Sacc[8][4];
        #pragma unroll
        for (int j = 0; j < 8; ++j)
            #pragma unroll
            for (int i = 0; i < 4; ++i) Sacc[j][i] = 0.0f;

        #pragma unroll
        for (int g = 0; g < 8; ++g) {
            const int off = (g ^ (lane & 7)) << 2;
            #pragma unroll
            for (int a = 0; a < 8; ++a) {
                const float4 kf = *(const float4*)(sm + KOFF + a * 1024 + lane * 32 + off);
                float bf0[2] = {kf.x, kf.y};
                float bf1[2] = {kf.z, kf.w};
                mma_tf32(Sacc[a], Qf[2 * g],     bf0);
                mma_tf32(Sacc[a], Qf[2 * g + 1], bf1);
            }
        }

        // ---- scale + adjacency bias (in place) ----
        float mx0 = -INFINITY, mx1 = -INFINITY;
        #pragma unroll
        for (int jn = 0; jn < 8; ++jn) {
            Sacc[jn][0] = fmaf(Sacc[jn][0], SCALE, A0[jn].x ? 0.0f : NEG_BIG);
            Sacc[jn][1] = fmaf(Sacc[jn][1], SCALE, A0[jn].y ? 0.0f : NEG_BIG);
            Sacc[jn][2] = fmaf(Sacc[jn][2], SCALE, A1[jn].x ? 0.0f : NEG_BIG);
            Sacc[jn][3] = fmaf(Sacc[jn][3], SCALE, A1[jn].y ? 0.0f : NEG_BIG);
            mx0 = fmaxf(mx0, fmaxf(Sacc[jn][0], Sacc[jn][1]));
            mx1 = fmaxf(mx1, fmaxf(Sacc[jn][2], Sacc[jn][3]));
        }
        mx0 = fmaxf(mx0, __shfl_xor_sync(0xffffffffu, mx0, 1));
        mx0 = fmaxf(mx0, __shfl_xor_sync(0xffffffffu, mx0, 2));
        mx1 = fmaxf(mx1, __shfl_xor_sync(0xffffffffu, mx1, 1));
        mx1 = fmaxf(mx1, __shfl_xor_sync(0xffffffffu, mx1, 2));

        const float mn0 = fmaxf(m0, mx0);
        const float mn1 = fmaxf(m1, mx1);
        const float alpha0 = __expf(m0 - mn0);
        const float alpha1 = __expf(m1 - mn1);
        m0 = mn0; m1 = mn1;

        float sum0 = 0.0f, sum1 = 0.0f;
        #pragma unroll
        for (int jn = 0; jn < 8; ++jn) {
            Sacc[jn][0] = __expf(Sacc[jn][0] - mn0);
            Sacc[jn][1] = __expf(Sacc[jn][1] - mn0);
            Sacc[jn][2] = __expf(Sacc[jn][2] - mn1);
            Sacc[jn][3] = __expf(Sacc[jn][3] - mn1);
            sum0 += Sacc[jn][0] + Sacc[jn][1];
            sum1 += Sacc[jn][2] + Sacc[jn][3];
            float2* d0 = (float2*)(Ps + (16 * w + qr) * PSTRIDE + 8 * jn + 2 * qc);
            float2* d1 = (float2*)(Ps + (16 * w + qr + 8) * PSTRIDE + 8 * jn + 2 * qc);
            *d0 = make_float2(to_tf32(Sacc[jn][0]), to_tf32(Sacc[jn][1]));
            *d1 = make_float2(to_tf32(Sacc[jn][2]), to_tf32(Sacc[jn][3]));
        }
        sum0 += __shfl_xor_sync(0xffffffffu, sum0, 1);
        sum0 += __shfl_xor_sync(0xffffffffu, sum0, 2);
        sum1 += __shfl_xor_sync(0xffffffffu, sum1, 1);
        sum1 += __shfl_xor_sync(0xffffffffu, sum1, 2);
        l0 = l0 * alpha0 + sum0;
        l1 = l1 * alpha1 + sum1;

        #pragma unroll
        for (int jn = 0; jn < 16; ++jn) {
            O[jn][0] *= alpha0; O[jn][1] *= alpha0;
            O[jn][2] *= alpha1; O[jn][3] *= alpha1;
        }

        __syncwarp();   // P visible to quad-mates

        // ---- O += P V ----
        #pragma unroll
        for (int g = 0; g < 4; ++g) {
            float a0[4], a1[4];
            const float* pp0 = Ps + (16 * w + qr) * PSTRIDE + 16 * g + qc;
            a0[0] = pp0[0];
            a0[1] = pp0[8 * PSTRIDE];
            a0[2] = pp0[4];
            a0[3] = pp0[8 * PSTRIDE + 4];
            a1[0] = pp0[8];
            a1[1] = pp0[8 * PSTRIDE + 8];
            a1[2] = pp0[12];
            a1[3] = pp0[8 * PSTRIDE + 12];
            const int sw = ((lane >> 1) & 3);
            #pragma unroll
            for (int a = 0; a < 16; ++a) {
                const float* vb = sm + VOFF + a * 512 + lane * 16;
                const float4 vf = *(const float4*)(vb + ((g ^ sw) << 2));
                float bf0[2] = {vf.x, vf.y};
                float bf1[2] = {vf.z, vf.w};
                mma_tf32(O[a], a0, bf0);
                mma_tf32(O[a], a1, bf1);
            }
        }

        __syncthreads();   // all K/V/Ps reads done before next chunk's copy
    }

    // ---- epilogue: normalize, ELU, store ----
    {
        const float li0 = 1.0f / l0;
        const float li1 = 1.0f / l1;
        float* out0 = out + ((size_t)b * SEQ + r0g) * DIM;
        float* out1 = out + ((size_t)b * SEQ + r1g) * DIM;
        #pragma unroll
        for (int jn = 0; jn < 16; ++jn) {
            const int col = 8 * jn + 2 * qc;
            *(float2*)(out0 + col) =
                make_float2(elu1(O[jn][0] * li0), elu1(O[jn][1] * li0));
            *(float2*)(out1 + col) =
                make_float2(elu1(O[jn][2] * li1), elu1(O[jn][3] * li1));
        }
    }
}

// ---------------------------------------------------------------------------
extern "C" void kernel_launch(void* const* d_in, const int* in_sizes, int n_in,
                              void* d_out, int out_size)
{
    const float* x   = (const float*)d_in[0];
    const int*   adj = (const int*)  d_in[1];
    const float* Wq  = (const float*)d_in[2];
    const float* bq  = (const float*)d_in[3];
    const float* Wk  = (const float*)d_in[4];
    const float* bk  = (const float*)d_in[5];
    const float* Wv  = (const float*)d_in[6];
    const float* bv  = (const float*)d_in[7];
    float* out = (float*)d_out;

    cudaFuncSetAttribute(proj_kernel,
                         cudaFuncAttributeMaxDynamicSharedMemorySize, PSM_BYTES);
    cudaFuncSetAttribute(attn_kernel,
                         cudaFuncAttributeMaxDynamicSharedMemorySize, SMEM_BYTES);

    proj_kernel<<<(BATCH * SEQ) / 128, 256, PSM_BYTES>>>(
        x, Wq, bq, Wk, bk, Wv, bv);

    attn_kernel<<<dim3(SEQ / BR, BATCH), 128, SMEM_BYTES>>>(adj, out);
}